// round 1
// baseline (speedup 1.0000x reference)
#include <cuda_runtime.h>
#include <math_constants.h>

#define B_  2
#define S_  2048
#define DM  1024
#define DK  64
#define H_  16
#define BH  (B_ * H_)
#define ROWS (B_ * S_)          // 4096

// Scratch (allocation-free: device globals)
__device__ float g_q[BH * S_ * DK];
__device__ float g_k[BH * S_ * DK];
__device__ float g_v[BH * S_ * DK];
__device__ float g_ctx[ROWS * DM];

// ---------------------------------------------------------------------------
// Kernel 1: fused per-head QKV projection.
// grid = (ROWS/64, H, 3), block = 256. Computes a 64x64 tile of
// out[proj] = X(4096x1024) @ W_proj_h(1024x64).
// ---------------------------------------------------------------------------
__global__ __launch_bounds__(256) void qkv_proj_kernel(
    const float* __restrict__ x,
    const float* __restrict__ Wq,
    const float* __restrict__ Wk,
    const float* __restrict__ Wv)
{
    __shared__ float As[16][65];   // k-major, padded
    __shared__ float Bs[16][64];

    const int t  = threadIdx.x;
    const int tx = t & 15;
    const int ty = t >> 4;
    const int row0 = blockIdx.x * 64;
    const int h    = blockIdx.y;
    const int p    = blockIdx.z;

    const float* W = (p == 0 ? Wq : (p == 1 ? Wk : Wv)) + h * DM * DK;
    float* out     = (p == 0 ? g_q : (p == 1 ? g_k : g_v));

    const int aRow = t >> 2, aCol = (t & 3) * 4;
    const int bRow = t >> 4, bCol = (t & 15) * 4;

    float acc[4][4] = {};

    for (int k0 = 0; k0 < DM; k0 += 16) {
        float4 av = *(const float4*)&x[(row0 + aRow) * DM + k0 + aCol];
        As[aCol + 0][aRow] = av.x;
        As[aCol + 1][aRow] = av.y;
        As[aCol + 2][aRow] = av.z;
        As[aCol + 3][aRow] = av.w;
        *(float4*)&Bs[bRow][bCol] = *(const float4*)&W[(k0 + bRow) * DK + bCol];
        __syncthreads();

        #pragma unroll
        for (int kk = 0; kk < 16; kk++) {
            float a0 = As[kk][4 * ty + 0];
            float a1 = As[kk][4 * ty + 1];
            float a2 = As[kk][4 * ty + 2];
            float a3 = As[kk][4 * ty + 3];
            float4 b4 = *(float4*)&Bs[kk][4 * tx];
            acc[0][0] += a0 * b4.x; acc[0][1] += a0 * b4.y; acc[0][2] += a0 * b4.z; acc[0][3] += a0 * b4.w;
            acc[1][0] += a1 * b4.x; acc[1][1] += a1 * b4.y; acc[1][2] += a1 * b4.z; acc[1][3] += a1 * b4.w;
            acc[2][0] += a2 * b4.x; acc[2][1] += a2 * b4.y; acc[2][2] += a2 * b4.z; acc[2][3] += a2 * b4.w;
            acc[3][0] += a3 * b4.x; acc[3][1] += a3 * b4.y; acc[3][2] += a3 * b4.z; acc[3][3] += a3 * b4.w;
        }
        __syncthreads();
    }

    #pragma unroll
    for (int i = 0; i < 4; i++) {
        int r = row0 + 4 * ty + i;
        int b = r >> 11, s = r & (S_ - 1);
        float4 o = make_float4(acc[i][0], acc[i][1], acc[i][2], acc[i][3]);
        *(float4*)&out[(((b * H_) + h) * S_ + s) * DK + 4 * tx] = o;
    }
}

// ---------------------------------------------------------------------------
// Kernel 2: flash attention per (b,h), 64-query tiles.
// grid = (S/64, B*H), block = 256, dynamic smem 65792 B.
// ---------------------------------------------------------------------------
#define ATTN_SMEM (4 * (3 * 4096 + 64 * 65))   // 65792 bytes

__global__ __launch_bounds__(256) void attention_kernel()
{
    extern __shared__ float sm[];
    float* Qt = sm;                 // [64][64], d-major:   Qt[d*64 + qrow]
    float* Kt = sm + 4096;          // [64][64], d-major:   Kt[d*64 + krow]
    float* Vs = sm + 8192;          // [64][64], key-major: Vs[k*64 + vcol]
    float* Ps = sm + 12288;         // [64][65], row-major padded

    const int t  = threadIdx.x;
    const int tx = t & 15;
    const int ty = t >> 4;
    const int bh = blockIdx.y;
    const int q0 = blockIdx.x * 64;

    const float* qb = g_q + (size_t)bh * S_ * DK;
    const float* kb = g_k + (size_t)bh * S_ * DK;
    const float* vb = g_v + (size_t)bh * S_ * DK;

    // Load + pre-scale Q tile (transposed, d-major)
    const float scale = 0.125f;    // 1/sqrt(64)
    for (int i = t * 4; i < 4096; i += 1024) {
        int r = i >> 6, c = i & 63;
        float4 qv = *(const float4*)&qb[(q0 + r) * DK + c];
        Qt[(c + 0) * 64 + r] = qv.x * scale;
        Qt[(c + 1) * 64 + r] = qv.y * scale;
        Qt[(c + 2) * 64 + r] = qv.z * scale;
        Qt[(c + 3) * 64 + r] = qv.w * scale;
    }

    float m[4], l[4], acc[4][4];
    #pragma unroll
    for (int i = 0; i < 4; i++) {
        m[i] = -CUDART_INF_F; l[i] = 0.f;
        #pragma unroll
        for (int j = 0; j < 4; j++) acc[i][j] = 0.f;
    }

    for (int kt = 0; kt < S_ / 64; kt++) {
        __syncthreads();  // previous PV done with Vs/Ps; Q load done (iter 0)
        for (int i = t * 4; i < 4096; i += 1024) {
            int r = i >> 6, c = i & 63;
            float4 kv = *(const float4*)&kb[(kt * 64 + r) * DK + c];
            Kt[(c + 0) * 64 + r] = kv.x;
            Kt[(c + 1) * 64 + r] = kv.y;
            Kt[(c + 2) * 64 + r] = kv.z;
            Kt[(c + 3) * 64 + r] = kv.w;
            *(float4*)&Vs[r * 64 + c] = *(const float4*)&vb[(kt * 64 + r) * DK + c];
        }
        __syncthreads();

        // scores tile S = Q K^T  (4x4 per thread)
        float s[4][4] = {};
        #pragma unroll
        for (int d = 0; d < 64; d++) {
            float4 a4 = *(float4*)&Qt[d * 64 + 4 * ty];
            float4 b4 = *(float4*)&Kt[d * 64 + 4 * tx];
            s[0][0] += a4.x * b4.x; s[0][1] += a4.x * b4.y; s[0][2] += a4.x * b4.z; s[0][3] += a4.x * b4.w;
            s[1][0] += a4.y * b4.x; s[1][1] += a4.y * b4.y; s[1][2] += a4.y * b4.z; s[1][3] += a4.y * b4.w;
            s[2][0] += a4.z * b4.x; s[2][1] += a4.z * b4.y; s[2][2] += a4.z * b4.z; s[2][3] += a4.z * b4.w;
            s[3][0] += a4.w * b4.x; s[3][1] += a4.w * b4.y; s[3][2] += a4.w * b4.z; s[3][3] += a4.w * b4.w;
        }

        // online softmax update (per query row; reduce over 16 lanes of same ty)
        #pragma unroll
        for (int i = 0; i < 4; i++) {
            float rm = fmaxf(fmaxf(s[i][0], s[i][1]), fmaxf(s[i][2], s[i][3]));
            #pragma unroll
            for (int off = 8; off; off >>= 1)
                rm = fmaxf(rm, __shfl_xor_sync(0xffffffffu, rm, off));
            float mn = fmaxf(m[i], rm);
            float alpha = __expf(m[i] - mn);
            m[i] = mn;
            float rs = 0.f;
            #pragma unroll
            for (int j = 0; j < 4; j++) {
                s[i][j] = __expf(s[i][j] - mn);
                rs += s[i][j];
            }
            #pragma unroll
            for (int off = 8; off; off >>= 1)
                rs += __shfl_xor_sync(0xffffffffu, rs, off);
            l[i] = l[i] * alpha + rs;
            #pragma unroll
            for (int j = 0; j < 4; j++) {
                acc[i][j] *= alpha;
                Ps[(4 * ty + i) * 65 + 4 * tx + j] = s[i][j];
            }
        }
        __syncthreads();

        // O += P @ V
        #pragma unroll
        for (int tt = 0; tt < 64; tt++) {
            float4 b4 = *(float4*)&Vs[tt * 64 + 4 * tx];
            float a0 = Ps[(4 * ty + 0) * 65 + tt];
            float a1 = Ps[(4 * ty + 1) * 65 + tt];
            float a2 = Ps[(4 * ty + 2) * 65 + tt];
            float a3 = Ps[(4 * ty + 3) * 65 + tt];
            acc[0][0] += a0 * b4.x; acc[0][1] += a0 * b4.y; acc[0][2] += a0 * b4.z; acc[0][3] += a0 * b4.w;
            acc[1][0] += a1 * b4.x; acc[1][1] += a1 * b4.y; acc[1][2] += a1 * b4.z; acc[1][3] += a1 * b4.w;
            acc[2][0] += a2 * b4.x; acc[2][1] += a2 * b4.y; acc[2][2] += a2 * b4.z; acc[2][3] += a2 * b4.w;
            acc[3][0] += a3 * b4.x; acc[3][1] += a3 * b4.y; acc[3][2] += a3 * b4.z; acc[3][3] += a3 * b4.w;
        }
    }

    // epilogue: ctx[b, s, h*64 + vcol] = acc / l
    const int b = bh >> 4;
    const int h = bh & 15;
    #pragma unroll
    for (int i = 0; i < 4; i++) {
        float inv = 1.f / l[i];
        int r = q0 + 4 * ty + i;
        float4 o = make_float4(acc[i][0] * inv, acc[i][1] * inv,
                               acc[i][2] * inv, acc[i][3] * inv);
        *(float4*)&g_ctx[((size_t)(b * S_ + r)) * DM + h * DK + 4 * tx] = o;
    }
}

// ---------------------------------------------------------------------------
// Kernel 3: output projection  out = ctx(4096x1024) @ Wo(1024x1024)
// grid = (ROWS/64, DM/64), block = 256
// ---------------------------------------------------------------------------
__global__ __launch_bounds__(256) void out_proj_kernel(
    const float* __restrict__ Wo, float* __restrict__ out)
{
    __shared__ float As[16][65];
    __shared__ float Bs[16][64];

    const int t  = threadIdx.x;
    const int tx = t & 15;
    const int ty = t >> 4;
    const int row0 = blockIdx.x * 64;
    const int col0 = blockIdx.y * 64;

    const int aRow = t >> 2, aCol = (t & 3) * 4;
    const int bRow = t >> 4, bCol = (t & 15) * 4;

    float acc[4][4] = {};

    for (int k0 = 0; k0 < DM; k0 += 16) {
        float4 av = *(const float4*)&g_ctx[(size_t)(row0 + aRow) * DM + k0 + aCol];
        As[aCol + 0][aRow] = av.x;
        As[aCol + 1][aRow] = av.y;
        As[aCol + 2][aRow] = av.z;
        As[aCol + 3][aRow] = av.w;
        *(float4*)&Bs[bRow][bCol] = *(const float4*)&Wo[(size_t)(k0 + bRow) * DM + col0 + bCol];
        __syncthreads();

        #pragma unroll
        for (int kk = 0; kk < 16; kk++) {
            float a0 = As[kk][4 * ty + 0];
            float a1 = As[kk][4 * ty + 1];
            float a2 = As[kk][4 * ty + 2];
            float a3 = As[kk][4 * ty + 3];
            float4 b4 = *(float4*)&Bs[kk][4 * tx];
            acc[0][0] += a0 * b4.x; acc[0][1] += a0 * b4.y; acc[0][2] += a0 * b4.z; acc[0][3] += a0 * b4.w;
            acc[1][0] += a1 * b4.x; acc[1][1] += a1 * b4.y; acc[1][2] += a1 * b4.z; acc[1][3] += a1 * b4.w;
            acc[2][0] += a2 * b4.x; acc[2][1] += a2 * b4.y; acc[2][2] += a2 * b4.z; acc[2][3] += a2 * b4.w;
            acc[3][0] += a3 * b4.x; acc[3][1] += a3 * b4.y; acc[3][2] += a3 * b4.z; acc[3][3] += a3 * b4.w;
        }
        __syncthreads();
    }

    #pragma unroll
    for (int i = 0; i < 4; i++) {
        float4 o = make_float4(acc[i][0], acc[i][1], acc[i][2], acc[i][3]);
        *(float4*)&out[(size_t)(row0 + 4 * ty + i) * DM + col0 + 4 * tx] = o;
    }
}

// ---------------------------------------------------------------------------
// Launch. Input order per metadata: x, Wk, Wq, Wv, Wo
// ---------------------------------------------------------------------------
extern "C" void kernel_launch(void* const* d_in, const int* in_sizes, int n_in,
                              void* d_out, int out_size)
{
    const float* x  = (const float*)d_in[0];
    const float* Wk = (const float*)d_in[1];
    const float* Wq = (const float*)d_in[2];
    const float* Wv = (const float*)d_in[3];
    const float* Wo = (const float*)d_in[4];
    float* out = (float*)d_out;

    cudaFuncSetAttribute(attention_kernel,
                         cudaFuncAttributeMaxDynamicSharedMemorySize, ATTN_SMEM);

    qkv_proj_kernel<<<dim3(ROWS / 64, H_, 3), 256>>>(x, Wq, Wk, Wv);
    attention_kernel<<<dim3(S_ / 64, BH), 256, ATTN_SMEM>>>();
    out_proj_kernel<<<dim3(ROWS / 64, DM / 64), 256>>>(Wo, out);
}

// round 2
// speedup vs baseline: 1.0005x; 1.0005x over previous
#include <cuda_runtime.h>
#include <math_constants.h>

#define B_  2
#define S_  2048
#define DM  1024
#define DK  64
#define H_  16
#define BH  (B_ * H_)
#define ROWS (B_ * S_)          // 4096

// Scratch (allocation-free: device globals)
__device__ float g_q[BH * S_ * DK];
__device__ float g_k[BH * S_ * DK];
__device__ float g_v[BH * S_ * DK];
__device__ float g_ctx[ROWS * DM];

// ---------------------------------------------------------------------------
// Kernel 1: fused per-head QKV projection.
// grid = (ROWS/64, H, 3), block = 256. Computes a 64x64 tile of
// out[proj] = X(4096x1024) @ W_proj_h(1024x64).
// ---------------------------------------------------------------------------
__global__ __launch_bounds__(256) void qkv_proj_kernel(
    const float* __restrict__ x,
    const float* __restrict__ Wq,
    const float* __restrict__ Wk,
    const float* __restrict__ Wv)
{
    __shared__ float As[16][65];   // k-major, padded
    __shared__ float Bs[16][64];

    const int t  = threadIdx.x;
    const int tx = t & 15;
    const int ty = t >> 4;
    const int row0 = blockIdx.x * 64;
    const int h    = blockIdx.y;
    const int p    = blockIdx.z;

    const float* W = (p == 0 ? Wq : (p == 1 ? Wk : Wv)) + h * DM * DK;
    float* out     = (p == 0 ? g_q : (p == 1 ? g_k : g_v));

    const int aRow = t >> 2, aCol = (t & 3) * 4;
    const int bRow = t >> 4, bCol = (t & 15) * 4;

    float acc[4][4] = {};

    for (int k0 = 0; k0 < DM; k0 += 16) {
        float4 av = *(const float4*)&x[(row0 + aRow) * DM + k0 + aCol];
        As[aCol + 0][aRow] = av.x;
        As[aCol + 1][aRow] = av.y;
        As[aCol + 2][aRow] = av.z;
        As[aCol + 3][aRow] = av.w;
        *(float4*)&Bs[bRow][bCol] = *(const float4*)&W[(k0 + bRow) * DK + bCol];
        __syncthreads();

        #pragma unroll
        for (int kk = 0; kk < 16; kk++) {
            float a0 = As[kk][4 * ty + 0];
            float a1 = As[kk][4 * ty + 1];
            float a2 = As[kk][4 * ty + 2];
            float a3 = As[kk][4 * ty + 3];
            float4 b4 = *(float4*)&Bs[kk][4 * tx];
            acc[0][0] += a0 * b4.x; acc[0][1] += a0 * b4.y; acc[0][2] += a0 * b4.z; acc[0][3] += a0 * b4.w;
            acc[1][0] += a1 * b4.x; acc[1][1] += a1 * b4.y; acc[1][2] += a1 * b4.z; acc[1][3] += a1 * b4.w;
            acc[2][0] += a2 * b4.x; acc[2][1] += a2 * b4.y; acc[2][2] += a2 * b4.z; acc[2][3] += a2 * b4.w;
            acc[3][0] += a3 * b4.x; acc[3][1] += a3 * b4.y; acc[3][2] += a3 * b4.z; acc[3][3] += a3 * b4.w;
        }
        __syncthreads();
    }

    #pragma unroll
    for (int i = 0; i < 4; i++) {
        int r = row0 + 4 * ty + i;
        int b = r >> 11, s = r & (S_ - 1);
        float4 o = make_float4(acc[i][0], acc[i][1], acc[i][2], acc[i][3]);
        *(float4*)&out[(((b * H_) + h) * S_ + s) * DK + 4 * tx] = o;
    }
}

// ---------------------------------------------------------------------------
// Kernel 2: flash attention per (b,h), 64-query tiles.
// grid = (S/64, B*H), block = 256, dynamic smem 65792 B.
// ---------------------------------------------------------------------------
#define ATTN_SMEM (4 * (3 * 4096 + 64 * 65))   // 65792 bytes

__global__ __launch_bounds__(256) void attention_kernel()
{
    extern __shared__ float sm[];
    float* Qt = sm;                 // [64][64], d-major:   Qt[d*64 + qrow]
    float* Kt = sm + 4096;          // [64][64], d-major:   Kt[d*64 + krow]
    float* Vs = sm + 8192;          // [64][64], key-major: Vs[k*64 + vcol]
    float* Ps = sm + 12288;         // [64][65], row-major padded

    const int t  = threadIdx.x;
    const int tx = t & 15;
    const int ty = t >> 4;
    const int bh = blockIdx.y;
    const int q0 = blockIdx.x * 64;

    const float* qb = g_q + (size_t)bh * S_ * DK;
    const float* kb = g_k + (size_t)bh * S_ * DK;
    const float* vb = g_v + (size_t)bh * S_ * DK;

    // Load + pre-scale Q tile (transposed, d-major)
    const float scale = 0.125f;    // 1/sqrt(64)
    for (int i = t * 4; i < 4096; i += 1024) {
        int r = i >> 6, c = i & 63;
        float4 qv = *(const float4*)&qb[(q0 + r) * DK + c];
        Qt[(c + 0) * 64 + r] = qv.x * scale;
        Qt[(c + 1) * 64 + r] = qv.y * scale;
        Qt[(c + 2) * 64 + r] = qv.z * scale;
        Qt[(c + 3) * 64 + r] = qv.w * scale;
    }

    float m[4], l[4], acc[4][4];
    #pragma unroll
    for (int i = 0; i < 4; i++) {
        m[i] = -CUDART_INF_F; l[i] = 0.f;
        #pragma unroll
        for (int j = 0; j < 4; j++) acc[i][j] = 0.f;
    }

    for (int kt = 0; kt < S_ / 64; kt++) {
        __syncthreads();  // previous PV done with Vs/Ps; Q load done (iter 0)
        for (int i = t * 4; i < 4096; i += 1024) {
            int r = i >> 6, c = i & 63;
            float4 kv = *(const float4*)&kb[(kt * 64 + r) * DK + c];
            Kt[(c + 0) * 64 + r] = kv.x;
            Kt[(c + 1) * 64 + r] = kv.y;
            Kt[(c + 2) * 64 + r] = kv.z;
            Kt[(c + 3) * 64 + r] = kv.w;
            *(float4*)&Vs[r * 64 + c] = *(const float4*)&vb[(kt * 64 + r) * DK + c];
        }
        __syncthreads();

        // scores tile S = Q K^T  (4x4 per thread)
        float s[4][4] = {};
        #pragma unroll
        for (int d = 0; d < 64; d++) {
            float4 a4 = *(float4*)&Qt[d * 64 + 4 * ty];
            float4 b4 = *(float4*)&Kt[d * 64 + 4 * tx];
            s[0][0] += a4.x * b4.x; s[0][1] += a4.x * b4.y; s[0][2] += a4.x * b4.z; s[0][3] += a4.x * b4.w;
            s[1][0] += a4.y * b4.x; s[1][1] += a4.y * b4.y; s[1][2] += a4.y * b4.z; s[1][3] += a4.y * b4.w;
            s[2][0] += a4.z * b4.x; s[2][1] += a4.z * b4.y; s[2][2] += a4.z * b4.z; s[2][3] += a4.z * b4.w;
            s[3][0] += a4.w * b4.x; s[3][1] += a4.w * b4.y; s[3][2] += a4.w * b4.z; s[3][3] += a4.w * b4.w;
        }

        // online softmax update (per query row; reduce over 16 lanes of same ty)
        #pragma unroll
        for (int i = 0; i < 4; i++) {
            float rm = fmaxf(fmaxf(s[i][0], s[i][1]), fmaxf(s[i][2], s[i][3]));
            #pragma unroll
            for (int off = 8; off; off >>= 1)
                rm = fmaxf(rm, __shfl_xor_sync(0xffffffffu, rm, off));
            float mn = fmaxf(m[i], rm);
            float alpha = __expf(m[i] - mn);
            m[i] = mn;
            float rs = 0.f;
            #pragma unroll
            for (int j = 0; j < 4; j++) {
                s[i][j] = __expf(s[i][j] - mn);
                rs += s[i][j];
            }
            #pragma unroll
            for (int off = 8; off; off >>= 1)
                rs += __shfl_xor_sync(0xffffffffu, rs, off);
            l[i] = l[i] * alpha + rs;
            #pragma unroll
            for (int j = 0; j < 4; j++) {
                acc[i][j] *= alpha;
                Ps[(4 * ty + i) * 65 + 4 * tx + j] = s[i][j];
            }
        }
        __syncthreads();

        // O += P @ V
        #pragma unroll
        for (int tt = 0; tt < 64; tt++) {
            float4 b4 = *(float4*)&Vs[tt * 64 + 4 * tx];
            float a0 = Ps[(4 * ty + 0) * 65 + tt];
            float a1 = Ps[(4 * ty + 1) * 65 + tt];
            float a2 = Ps[(4 * ty + 2) * 65 + tt];
            float a3 = Ps[(4 * ty + 3) * 65 + tt];
            acc[0][0] += a0 * b4.x; acc[0][1] += a0 * b4.y; acc[0][2] += a0 * b4.z; acc[0][3] += a0 * b4.w;
            acc[1][0] += a1 * b4.x; acc[1][1] += a1 * b4.y; acc[1][2] += a1 * b4.z; acc[1][3] += a1 * b4.w;
            acc[2][0] += a2 * b4.x; acc[2][1] += a2 * b4.y; acc[2][2] += a2 * b4.z; acc[2][3] += a2 * b4.w;
            acc[3][0] += a3 * b4.x; acc[3][1] += a3 * b4.y; acc[3][2] += a3 * b4.z; acc[3][3] += a3 * b4.w;
        }
    }

    // epilogue: ctx[b, s, h*64 + vcol] = acc / l
    const int b = bh >> 4;
    const int h = bh & 15;
    #pragma unroll
    for (int i = 0; i < 4; i++) {
        float inv = 1.f / l[i];
        int r = q0 + 4 * ty + i;
        float4 o = make_float4(acc[i][0] * inv, acc[i][1] * inv,
                               acc[i][2] * inv, acc[i][3] * inv);
        *(float4*)&g_ctx[((size_t)(b * S_ + r)) * DM + h * DK + 4 * tx] = o;
    }
}

// ---------------------------------------------------------------------------
// Kernel 3: output projection  out = ctx(4096x1024) @ Wo(1024x1024)
// grid = (ROWS/64, DM/64), block = 256
// ---------------------------------------------------------------------------
__global__ __launch_bounds__(256) void out_proj_kernel(
    const float* __restrict__ Wo, float* __restrict__ out)
{
    __shared__ float As[16][65];
    __shared__ float Bs[16][64];

    const int t  = threadIdx.x;
    const int tx = t & 15;
    const int ty = t >> 4;
    const int row0 = blockIdx.x * 64;
    const int col0 = blockIdx.y * 64;

    const int aRow = t >> 2, aCol = (t & 3) * 4;
    const int bRow = t >> 4, bCol = (t & 15) * 4;

    float acc[4][4] = {};

    for (int k0 = 0; k0 < DM; k0 += 16) {
        float4 av = *(const float4*)&g_ctx[(size_t)(row0 + aRow) * DM + k0 + aCol];
        As[aCol + 0][aRow] = av.x;
        As[aCol + 1][aRow] = av.y;
        As[aCol + 2][aRow] = av.z;
        As[aCol + 3][aRow] = av.w;
        *(float4*)&Bs[bRow][bCol] = *(const float4*)&Wo[(size_t)(k0 + bRow) * DM + col0 + bCol];
        __syncthreads();

        #pragma unroll
        for (int kk = 0; kk < 16; kk++) {
            float a0 = As[kk][4 * ty + 0];
            float a1 = As[kk][4 * ty + 1];
            float a2 = As[kk][4 * ty + 2];
            float a3 = As[kk][4 * ty + 3];
            float4 b4 = *(float4*)&Bs[kk][4 * tx];
            acc[0][0] += a0 * b4.x; acc[0][1] += a0 * b4.y; acc[0][2] += a0 * b4.z; acc[0][3] += a0 * b4.w;
            acc[1][0] += a1 * b4.x; acc[1][1] += a1 * b4.y; acc[1][2] += a1 * b4.z; acc[1][3] += a1 * b4.w;
            acc[2][0] += a2 * b4.x; acc[2][1] += a2 * b4.y; acc[2][2] += a2 * b4.z; acc[2][3] += a2 * b4.w;
            acc[3][0] += a3 * b4.x; acc[3][1] += a3 * b4.y; acc[3][2] += a3 * b4.z; acc[3][3] += a3 * b4.w;
        }
        __syncthreads();
    }

    #pragma unroll
    for (int i = 0; i < 4; i++) {
        float4 o = make_float4(acc[i][0], acc[i][1], acc[i][2], acc[i][3]);
        *(float4*)&out[(size_t)(row0 + 4 * ty + i) * DM + col0 + 4 * tx] = o;
    }
}

// ---------------------------------------------------------------------------
// Launch. Input order per metadata: x, Wk, Wq, Wv, Wo
// ---------------------------------------------------------------------------
extern "C" void kernel_launch(void* const* d_in, const int* in_sizes, int n_in,
                              void* d_out, int out_size)
{
    const float* x  = (const float*)d_in[0];
    const float* Wk = (const float*)d_in[1];
    const float* Wq = (const float*)d_in[2];
    const float* Wv = (const float*)d_in[3];
    const float* Wo = (const float*)d_in[4];
    float* out = (float*)d_out;

    cudaFuncSetAttribute(attention_kernel,
                         cudaFuncAttributeMaxDynamicSharedMemorySize, ATTN_SMEM);

    qkv_proj_kernel<<<dim3(ROWS / 64, H_, 3), 256>>>(x, Wq, Wk, Wv);
    attention_kernel<<<dim3(S_ / 64, BH), 256, ATTN_SMEM>>>();
    out_proj_kernel<<<dim3(ROWS / 64, DM / 64), 256>>>(Wo, out);
}

// round 5
// speedup vs baseline: 2.9226x; 2.9210x over previous
#include <cuda_runtime.h>
#include <cuda_bf16.h>
#include <math_constants.h>
#include <cstdint>

#define B_  2
#define S_  2048
#define DM  1024
#define DK  64
#define H_  16
#define BH  (B_ * H_)
#define ROWS (B_ * S_)          // 4096

// ---------------------------------------------------------------------------
// Scratch (allocation-free: device globals)
// ---------------------------------------------------------------------------
__device__ __nv_bfloat16 g_xhi[ROWS * DM], g_xlo[ROWS * DM];
__device__ __nv_bfloat16 g_wq_hi[DM * DM], g_wq_lo[DM * DM];
__device__ __nv_bfloat16 g_wk_hi[DM * DM], g_wk_lo[DM * DM];
__device__ __nv_bfloat16 g_wv_hi[DM * DM], g_wv_lo[DM * DM];
__device__ __nv_bfloat16 g_wo_hi[DM * DM], g_wo_lo[DM * DM];
__device__ __nv_bfloat16 g_qhi[BH * S_ * DK], g_qlo[BH * S_ * DK];
__device__ __nv_bfloat16 g_khi[BH * S_ * DK], g_klo[BH * S_ * DK];
__device__ __nv_bfloat16 g_vhi[BH * S_ * DK], g_vlo[BH * S_ * DK];
__device__ __nv_bfloat16 g_cxhi[ROWS * DM], g_cxlo[ROWS * DM];

// ---------------------------------------------------------------------------
// Helpers: mma.sync / ldmatrix / cp.async (plain sm_80+ features only)
// ---------------------------------------------------------------------------
__device__ __forceinline__ uint32_t smem_to_u32(const void* p) {
    uint32_t a;
    asm("{ .reg .u64 t; cvta.to.shared.u64 t, %1; cvt.u32.u64 %0, t; }"
        : "=r"(a) : "l"(p));
    return a;
}
__device__ __forceinline__ void mma16816(float* c, const uint32_t* a, const uint32_t* b) {
    asm volatile("mma.sync.aligned.m16n8k16.row.col.f32.bf16.bf16.f32 "
        "{%0,%1,%2,%3}, {%4,%5,%6,%7}, {%8,%9}, {%0,%1,%2,%3};"
        : "+f"(c[0]), "+f"(c[1]), "+f"(c[2]), "+f"(c[3])
        : "r"(a[0]), "r"(a[1]), "r"(a[2]), "r"(a[3]), "r"(b[0]), "r"(b[1]));
}
__device__ __forceinline__ void ldsm_x4(uint32_t* r, uint32_t a) {
    asm volatile("ldmatrix.sync.aligned.m8n8.x4.shared.b16 {%0,%1,%2,%3}, [%4];"
        : "=r"(r[0]), "=r"(r[1]), "=r"(r[2]), "=r"(r[3]) : "r"(a));
}
__device__ __forceinline__ void ldsm_x4_t(uint32_t* r, uint32_t a) {
    asm volatile("ldmatrix.sync.aligned.m8n8.x4.trans.shared.b16 {%0,%1,%2,%3}, [%4];"
        : "=r"(r[0]), "=r"(r[1]), "=r"(r[2]), "=r"(r[3]) : "r"(a));
}
__device__ __forceinline__ void cp16(uint32_t d, const void* s) {
    asm volatile("cp.async.cg.shared.global [%0], [%1], 16;" :: "r"(d), "l"(s));
}
#define CP_COMMIT asm volatile("cp.async.commit_group;" ::: "memory")
#define CP_WAIT1  asm volatile("cp.async.wait_group 1;" ::: "memory")
#define CP_WAIT0  asm volatile("cp.async.wait_group 0;" ::: "memory")

// pack two floats as bf16x2 (first arg -> low half)
__device__ __forceinline__ uint32_t packbf(float lo, float hi) {
    uint32_t r;
    asm("cvt.rn.bf16x2.f32 %0, %1, %2;" : "=r"(r) : "f"(hi), "f"(lo));
    return r;
}
__device__ __forceinline__ float bf16rt(float v) {
    return __bfloat162float(__float2bfloat16(v));
}

// ---------------------------------------------------------------------------
// Prep kernels: fp32 -> bf16 hi/lo splits
// ---------------------------------------------------------------------------
__global__ void prep_x_kernel(const float* __restrict__ x,
                              __nv_bfloat16* __restrict__ hi,
                              __nv_bfloat16* __restrict__ lo, int n)
{
    for (int i = blockIdx.x * blockDim.x + threadIdx.x; i < n;
         i += gridDim.x * blockDim.x) {
        float v = x[i];
        __nv_bfloat16 h = __float2bfloat16(v);
        hi[i] = h;
        lo[i] = __float2bfloat16(v - __bfloat162float(h));
    }
}

// W[h][k][c] (16x1024x64) -> dst[n=h*64+c][k] bf16 hi/lo. grid (32,2,16), 256thr
__global__ void prep_w_heads_kernel(const float* __restrict__ W,
                                    __nv_bfloat16* __restrict__ hi,
                                    __nv_bfloat16* __restrict__ lo)
{
    __shared__ float tile[32][33];
    int t = threadIdx.x, tx = t & 31, ty = t >> 5;
    int k0 = blockIdx.x * 32, c0 = blockIdx.y * 32, h = blockIdx.z;
    const float* src = W + (size_t)h * DM * DK;
    #pragma unroll
    for (int i = 0; i < 32; i += 8)
        tile[ty + i][tx] = src[(size_t)(k0 + ty + i) * DK + c0 + tx];
    __syncthreads();
    #pragma unroll
    for (int i = 0; i < 32; i += 8) {
        int n = h * 64 + c0 + ty + i;
        float v = tile[tx][ty + i];
        __nv_bfloat16 hh = __float2bfloat16(v);
        hi[(size_t)n * DM + k0 + tx] = hh;
        lo[(size_t)n * DM + k0 + tx] = __float2bfloat16(v - __bfloat162float(hh));
    }
}

// Wo[k][n] (1024x1024) -> dst[n][k]. grid (32,32), 256thr
__global__ void prep_wo_kernel(const float* __restrict__ W,
                               __nv_bfloat16* __restrict__ hi,
                               __nv_bfloat16* __restrict__ lo)
{
    __shared__ float tile[32][33];
    int t = threadIdx.x, tx = t & 31, ty = t >> 5;
    int k0 = blockIdx.x * 32, n0 = blockIdx.y * 32;
    #pragma unroll
    for (int i = 0; i < 32; i += 8)
        tile[ty + i][tx] = W[(size_t)(k0 + ty + i) * DM + n0 + tx];
    __syncthreads();
    #pragma unroll
    for (int i = 0; i < 32; i += 8) {
        int n = n0 + ty + i;
        float v = tile[tx][ty + i];
        __nv_bfloat16 hh = __float2bfloat16(v);
        hi[(size_t)n * DM + k0 + tx] = hh;
        lo[(size_t)n * DM + k0 + tx] = __float2bfloat16(v - __bfloat162float(hh));
    }
}

// ---------------------------------------------------------------------------
// HMMA bf16-split GEMM: C[4096x1024] = A[4096x1024] * B^T (B stored [n][k])
// block 128x128, BK=32, 8 warps (warp tile 64x32), 2-stage cp.async pipeline.
// 3 products: Ahi*Bhi + Ahi*Blo + Alo*Bhi, fp32 accum.
// ---------------------------------------------------------------------------
#define GBK 32
#define GSTRIDE 40                      // padded bf16 elems per row (80 B)
#define GPLANE (128 * GSTRIDE * 2)      // 10240 B
#define GSTAGE (4 * GPLANE)             // 40960 B : Ahi,Alo,Bhi,Blo
#define GEMM_SMEM (2 * GSTAGE)          // 81920 B

__global__ __launch_bounds__(256) void gemm_mma(
    const __nv_bfloat16* __restrict__ Ahi, const __nv_bfloat16* __restrict__ Alo,
    const __nv_bfloat16* __restrict__ Bhi, const __nv_bfloat16* __restrict__ Blo,
    float* __restrict__ outf,
    __nv_bfloat16* __restrict__ outhi, __nv_bfloat16* __restrict__ outlo,
    float alpha, int mode)
{
    extern __shared__ char smem[];
    const uint32_t sb = smem_to_u32(smem);
    const int t = threadIdx.x, w = t >> 5, ln = t & 31;
    const int wm = (w & 1) * 64, wn = (w >> 1) * 32;
    const int row0 = blockIdx.x * 128, col0 = blockIdx.y * 128;

    const __nv_bfloat16* src[4] = {
        Ahi + (size_t)row0 * DM, Alo + (size_t)row0 * DM,
        Bhi + (size_t)col0 * DM, Blo + (size_t)col0 * DM };

    const int ldr0 = t >> 2, ldseg = t & 3;   // 64 rows x 4 segs (32 elem rows)

    float c[4][4][4] = {};

    {
        #pragma unroll
        for (int pi = 0; pi < 4; pi++)
            #pragma unroll
            for (int j = 0; j < 2; j++) {
                int row = ldr0 + j * 64;
                cp16(sb + pi * GPLANE + row * 80 + ldseg * 16,
                     src[pi] + (size_t)row * DM + ldseg * 8);
            }
        CP_COMMIT;
    }

    for (int kc = 0; kc < DM / GBK; kc++) {
        if (kc + 1 < DM / GBK) {
            int k0 = (kc + 1) * GBK;
            uint32_t stn = sb + ((kc + 1) & 1) * GSTAGE;
            #pragma unroll
            for (int pi = 0; pi < 4; pi++)
                #pragma unroll
                for (int j = 0; j < 2; j++) {
                    int row = ldr0 + j * 64;
                    cp16(stn + pi * GPLANE + row * 80 + ldseg * 16,
                         src[pi] + (size_t)row * DM + k0 + ldseg * 8);
                }
            CP_COMMIT;
            CP_WAIT1;
        } else {
            CP_WAIT0;
        }
        __syncthreads();
        uint32_t st = sb + (kc & 1) * GSTAGE;

        #pragma unroll
        for (int ks = 0; ks < 2; ks++) {
            uint32_t bh[4][2], bl[4][2];
            #pragma unroll
            for (int np = 0; np < 2; np++) {
                uint32_t baddr = st + 2 * GPLANE
                    + (wn + np * 16 + ((ln >> 4) & 1) * 8 + (ln & 7)) * 80
                    + ks * 32 + ((ln >> 3) & 1) * 16;
                uint32_t r[4];
                ldsm_x4(r, baddr);
                bh[2*np][0] = r[0]; bh[2*np][1] = r[1];
                bh[2*np+1][0] = r[2]; bh[2*np+1][1] = r[3];
                ldsm_x4(r, baddr + GPLANE);
                bl[2*np][0] = r[0]; bl[2*np][1] = r[1];
                bl[2*np+1][0] = r[2]; bl[2*np+1][1] = r[3];
            }
            #pragma unroll
            for (int mi = 0; mi < 4; mi++) {
                uint32_t aaddr = st + (wm + mi * 16 + (ln & 15)) * 80
                               + ks * 32 + (ln >> 4) * 16;
                uint32_t ah[4], al[4];
                ldsm_x4(ah, aaddr);
                ldsm_x4(al, aaddr + GPLANE);
                #pragma unroll
                for (int ni = 0; ni < 4; ni++) {
                    mma16816(c[mi][ni], ah, bh[ni]);
                    mma16816(c[mi][ni], ah, bl[ni]);
                    mma16816(c[mi][ni], al, bh[ni]);
                }
            }
        }
        __syncthreads();
    }

    #pragma unroll
    for (int mi = 0; mi < 4; mi++) {
        int r = row0 + wm + mi * 16 + (ln >> 2);
        #pragma unroll
        for (int ni = 0; ni < 4; ni++) {
            int cc = col0 + wn + ni * 8 + 2 * (ln & 3);
            if (mode == 0) {
                *(float2*)&outf[(size_t)r * DM + cc] =
                    make_float2(c[mi][ni][0], c[mi][ni][1]);
                *(float2*)&outf[(size_t)(r + 8) * DM + cc] =
                    make_float2(c[mi][ni][2], c[mi][ni][3]);
            } else {
                int h = cc >> 6, d = cc & 63;
                #pragma unroll
                for (int rr = 0; rr < 2; rr++) {
                    int row = r + rr * 8;
                    int b = row >> 11, s = row & (S_ - 1);
                    size_t idx = ((size_t)((b << 4) + h) * S_ + s) * DK + d;
                    float v0 = c[mi][ni][2 * rr + 0] * alpha;
                    float v1 = c[mi][ni][2 * rr + 1] * alpha;
                    float h0 = bf16rt(v0), h1 = bf16rt(v1);
                    *(uint32_t*)&outhi[idx] = packbf(v0, v1);
                    *(uint32_t*)&outlo[idx] = packbf(v0 - h0, v1 - h1);
                }
            }
        }
    }
}

// ---------------------------------------------------------------------------
// HMMA flash attention. grid (S/128, BH), 8 warps. Warp = 16 q-rows x 64 t.
// K/V hi/lo tiles double-buffered via cp.async. P built by register
// reinterleave of score C-frags (no smem round trip).
// ---------------------------------------------------------------------------
#define AT_STRIDE 72                     // padded elems (144 B)
#define AT_PLANE (64 * AT_STRIDE * 2)    // 9216 B
#define AT_STAGE (4 * AT_PLANE)          // 36864 : Khi,Klo,Vhi,Vlo
#define ATT_SMEM (2 * AT_STAGE)          // 73728

__global__ __launch_bounds__(256) void attn_mma()
{
    extern __shared__ char smem[];
    const uint32_t sb = smem_to_u32(smem);
    const int t = threadIdx.x, w = t >> 5, ln = t & 31;
    const int bh = blockIdx.y, q0 = blockIdx.x * 128;
    const size_t hbase = (size_t)bh * S_ * DK;

    // Q fragments (pre-scaled by 1/8 at projection epilogue)
    uint32_t qh[4][4], ql[4][4];
    {
        int r = q0 + w * 16 + (ln >> 2);
        int cb = 2 * (ln & 3);
        #pragma unroll
        for (int ks = 0; ks < 4; ks++) {
            int c0 = ks * 16 + cb;
            qh[ks][0] = *(const uint32_t*)&g_qhi[hbase + (size_t)r * DK + c0];
            qh[ks][1] = *(const uint32_t*)&g_qhi[hbase + (size_t)(r + 8) * DK + c0];
            qh[ks][2] = *(const uint32_t*)&g_qhi[hbase + (size_t)r * DK + c0 + 8];
            qh[ks][3] = *(const uint32_t*)&g_qhi[hbase + (size_t)(r + 8) * DK + c0 + 8];
            ql[ks][0] = *(const uint32_t*)&g_qlo[hbase + (size_t)r * DK + c0];
            ql[ks][1] = *(const uint32_t*)&g_qlo[hbase + (size_t)(r + 8) * DK + c0];
            ql[ks][2] = *(const uint32_t*)&g_qlo[hbase + (size_t)r * DK + c0 + 8];
            ql[ks][3] = *(const uint32_t*)&g_qlo[hbase + (size_t)(r + 8) * DK + c0 + 8];
        }
    }

    float ctx[8][4] = {};
    float m0 = -CUDART_INF_F, m1 = -CUDART_INF_F, lsum0 = 0.f, lsum1 = 0.f;

    const __nv_bfloat16* gsrc[4] = { g_khi + hbase, g_klo + hbase,
                                     g_vhi + hbase, g_vlo + hbase };
    // FIXED loader geometry: rows are 64 elems = 128 B = 8 segments of 16 B.
    const int krow = t >> 3, kseg = t & 7;   // 32 rows x 8 segs; 2 row-batches

    {
        #pragma unroll
        for (int pi = 0; pi < 4; pi++)
            #pragma unroll
            for (int j = 0; j < 2; j++) {
                int row = krow + j * 32;
                cp16(sb + pi * AT_PLANE + row * 144 + kseg * 16,
                     gsrc[pi] + (size_t)row * DK + kseg * 8);
            }
        CP_COMMIT;
    }

    for (int it = 0; it < S_ / 64; it++) {
        if (it + 1 < S_ / 64) {
            uint32_t stn = sb + ((it + 1) & 1) * AT_STAGE;
            #pragma unroll
            for (int pi = 0; pi < 4; pi++)
                #pragma unroll
                for (int j = 0; j < 2; j++) {
                    int row = krow + j * 32;
                    cp16(stn + pi * AT_PLANE + row * 144 + kseg * 16,
                         gsrc[pi] + (size_t)((it + 1) * 64 + row) * DK + kseg * 8);
                }
            CP_COMMIT;
            CP_WAIT1;
        } else {
            CP_WAIT0;
        }
        __syncthreads();
        uint32_t st = sb + (it & 1) * AT_STAGE;

        // ---- scores: S = Q * K^T (3-product) ----
        float sc[8][4] = {};
        #pragma unroll
        for (int np = 0; np < 4; np++) {
            #pragma unroll
            for (int ks = 0; ks < 4; ks++) {
                uint32_t baddr = st
                    + (np * 16 + ((ln >> 4) & 1) * 8 + (ln & 7)) * 144
                    + ks * 32 + ((ln >> 3) & 1) * 16;
                uint32_t rh[4], rl[4];
                ldsm_x4(rh, baddr);
                ldsm_x4(rl, baddr + AT_PLANE);
                uint32_t b0[2] = { rh[0], rh[1] }, b1[2] = { rh[2], rh[3] };
                uint32_t l0[2] = { rl[0], rl[1] }, l1[2] = { rl[2], rl[3] };
                mma16816(sc[2*np],     qh[ks], b0);
                mma16816(sc[2*np],     qh[ks], l0);
                mma16816(sc[2*np],     ql[ks], b0);
                mma16816(sc[2*np+1],   qh[ks], b1);
                mma16816(sc[2*np+1],   qh[ks], l1);
                mma16816(sc[2*np+1],   ql[ks], b1);
            }
        }

        // ---- online softmax ----
        float rmax0 = -CUDART_INF_F, rmax1 = -CUDART_INF_F;
        #pragma unroll
        for (int nt = 0; nt < 8; nt++) {
            rmax0 = fmaxf(rmax0, fmaxf(sc[nt][0], sc[nt][1]));
            rmax1 = fmaxf(rmax1, fmaxf(sc[nt][2], sc[nt][3]));
        }
        rmax0 = fmaxf(rmax0, __shfl_xor_sync(0xffffffffu, rmax0, 1));
        rmax0 = fmaxf(rmax0, __shfl_xor_sync(0xffffffffu, rmax0, 2));
        rmax1 = fmaxf(rmax1, __shfl_xor_sync(0xffffffffu, rmax1, 1));
        rmax1 = fmaxf(rmax1, __shfl_xor_sync(0xffffffffu, rmax1, 2));
        float mn0 = fmaxf(m0, rmax0), mn1 = fmaxf(m1, rmax1);
        float a0 = __expf(m0 - mn0), a1 = __expf(m1 - mn1);
        m0 = mn0; m1 = mn1;
        float rs0 = 0.f, rs1 = 0.f;
        #pragma unroll
        for (int nt = 0; nt < 8; nt++) {
            sc[nt][0] = __expf(sc[nt][0] - m0);
            sc[nt][1] = __expf(sc[nt][1] - m0);
            sc[nt][2] = __expf(sc[nt][2] - m1);
            sc[nt][3] = __expf(sc[nt][3] - m1);
            rs0 += sc[nt][0] + sc[nt][1];
            rs1 += sc[nt][2] + sc[nt][3];
        }
        rs0 += __shfl_xor_sync(0xffffffffu, rs0, 1);
        rs0 += __shfl_xor_sync(0xffffffffu, rs0, 2);
        rs1 += __shfl_xor_sync(0xffffffffu, rs1, 1);
        rs1 += __shfl_xor_sync(0xffffffffu, rs1, 2);
        lsum0 = lsum0 * a0 + rs0;
        lsum1 = lsum1 * a1 + rs1;
        #pragma unroll
        for (int vt = 0; vt < 8; vt++) {
            ctx[vt][0] *= a0; ctx[vt][1] *= a0;
            ctx[vt][2] *= a1; ctx[vt][3] *= a1;
        }

        // ---- P fragments by register reinterleave ----
        uint32_t ph[4][4], pl[4][4];
        #pragma unroll
        for (int j = 0; j < 4; j++) {
            #pragma unroll
            for (int e = 0; e < 4; e++) {
                int tile = 2 * j + (e >> 1);
                int o = (e & 1) * 2;
                float x = sc[tile][o], y = sc[tile][o + 1];
                ph[j][e] = packbf(x, y);
                pl[j][e] = packbf(x - bf16rt(x), y - bf16rt(y));
            }
        }

        // ---- ctx += P * V (3-product); V via ldsm.trans ----
        #pragma unroll
        for (int ks = 0; ks < 4; ks++) {
            #pragma unroll
            for (int np = 0; np < 4; np++) {
                uint32_t vaddr = st + 2 * AT_PLANE
                    + (ks * 16 + ((ln >> 3) & 1) * 8 + (ln & 7)) * 144
                    + np * 32 + ((ln >> 4) & 1) * 16;
                uint32_t rh[4], rl[4];
                ldsm_x4_t(rh, vaddr);
                ldsm_x4_t(rl, vaddr + AT_PLANE);
                uint32_t b0[2] = { rh[0], rh[1] }, b1[2] = { rh[2], rh[3] };
                uint32_t l0[2] = { rl[0], rl[1] }, l1[2] = { rl[2], rl[3] };
                mma16816(ctx[2*np],   ph[ks], b0);
                mma16816(ctx[2*np],   ph[ks], l0);
                mma16816(ctx[2*np],   pl[ks], b0);
                mma16816(ctx[2*np+1], ph[ks], b1);
                mma16816(ctx[2*np+1], ph[ks], l1);
                mma16816(ctx[2*np+1], pl[ks], b1);
            }
        }
        __syncthreads();
    }

    // ---- epilogue ----
    float inv0 = 1.f / lsum0, inv1 = 1.f / lsum1;
    const int b = bh >> 4, h = bh & 15;
    int r = q0 + w * 16 + (ln >> 2);
    size_t ob0 = ((size_t)(b * S_ + r)) * DM + h * 64;
    size_t ob1 = ob0 + (size_t)8 * DM;
    #pragma unroll
    for (int vt = 0; vt < 8; vt++) {
        int cc = vt * 8 + 2 * (ln & 3);
        float v0 = ctx[vt][0] * inv0, v1 = ctx[vt][1] * inv0;
        float v2 = ctx[vt][2] * inv1, v3 = ctx[vt][3] * inv1;
        *(uint32_t*)&g_cxhi[ob0 + cc] = packbf(v0, v1);
        *(uint32_t*)&g_cxlo[ob0 + cc] = packbf(v0 - bf16rt(v0), v1 - bf16rt(v1));
        *(uint32_t*)&g_cxhi[ob1 + cc] = packbf(v2, v3);
        *(uint32_t*)&g_cxlo[ob1 + cc] = packbf(v2 - bf16rt(v2), v3 - bf16rt(v3));
    }
}

// ---------------------------------------------------------------------------
// Launch. Input order per metadata: x, Wk, Wq, Wv, Wo
// ---------------------------------------------------------------------------
extern "C" void kernel_launch(void* const* d_in, const int* in_sizes, int n_in,
                              void* d_out, int out_size)
{
    const float* x  = (const float*)d_in[0];
    const float* Wk = (const float*)d_in[1];
    const float* Wq = (const float*)d_in[2];
    const float* Wv = (const float*)d_in[3];
    const float* Wo = (const float*)d_in[4];
    float* out = (float*)d_out;

    cudaFuncSetAttribute(gemm_mma,
                         cudaFuncAttributeMaxDynamicSharedMemorySize, GEMM_SMEM);
    cudaFuncSetAttribute(attn_mma,
                         cudaFuncAttributeMaxDynamicSharedMemorySize, ATT_SMEM);

    __nv_bfloat16 *xhi, *xlo, *wqh, *wql, *wkh, *wkl, *wvh, *wvl, *woh, *wol;
    __nv_bfloat16 *qhi, *qlo, *khi, *klo, *vhi, *vlo, *cxh, *cxl;
    cudaGetSymbolAddress((void**)&xhi, g_xhi);
    cudaGetSymbolAddress((void**)&xlo, g_xlo);
    cudaGetSymbolAddress((void**)&wqh, g_wq_hi);
    cudaGetSymbolAddress((void**)&wql, g_wq_lo);
    cudaGetSymbolAddress((void**)&wkh, g_wk_hi);
    cudaGetSymbolAddress((void**)&wkl, g_wk_lo);
    cudaGetSymbolAddress((void**)&wvh, g_wv_hi);
    cudaGetSymbolAddress((void**)&wvl, g_wv_lo);
    cudaGetSymbolAddress((void**)&woh, g_wo_hi);
    cudaGetSymbolAddress((void**)&wol, g_wo_lo);
    cudaGetSymbolAddress((void**)&qhi, g_qhi);
    cudaGetSymbolAddress((void**)&qlo, g_qlo);
    cudaGetSymbolAddress((void**)&khi, g_khi);
    cudaGetSymbolAddress((void**)&klo, g_klo);
    cudaGetSymbolAddress((void**)&vhi, g_vhi);
    cudaGetSymbolAddress((void**)&vlo, g_vlo);
    cudaGetSymbolAddress((void**)&cxh, g_cxhi);
    cudaGetSymbolAddress((void**)&cxl, g_cxlo);

    prep_x_kernel<<<1024, 256>>>(x, xhi, xlo, ROWS * DM);
    prep_w_heads_kernel<<<dim3(32, 2, 16), 256>>>(Wq, wqh, wql);
    prep_w_heads_kernel<<<dim3(32, 2, 16), 256>>>(Wk, wkh, wkl);
    prep_w_heads_kernel<<<dim3(32, 2, 16), 256>>>(Wv, wvh, wvl);
    prep_wo_kernel<<<dim3(32, 32), 256>>>(Wo, woh, wol);

    gemm_mma<<<dim3(32, 8), 256, GEMM_SMEM>>>(xhi, xlo, wqh, wql,
                                              nullptr, qhi, qlo, 0.125f, 1);
    gemm_mma<<<dim3(32, 8), 256, GEMM_SMEM>>>(xhi, xlo, wkh, wkl,
                                              nullptr, khi, klo, 1.0f, 1);
    gemm_mma<<<dim3(32, 8), 256, GEMM_SMEM>>>(xhi, xlo, wvh, wvl,
                                              nullptr, vhi, vlo, 1.0f, 1);

    attn_mma<<<dim3(S_ / 128, BH), 256, ATT_SMEM>>>();

    gemm_mma<<<dim3(32, 8), 256, GEMM_SMEM>>>(cxh, cxl, woh, wol,
                                              out, nullptr, nullptr, 1.0f, 0);
}

// round 6
// speedup vs baseline: 3.1164x; 1.0663x over previous
#include <cuda_runtime.h>
#include <cuda_bf16.h>
#include <math_constants.h>
#include <cstdint>

#define B_  2
#define S_  2048
#define DM  1024
#define DK  64
#define H_  16
#define BH  (B_ * H_)
#define ROWS (B_ * S_)          // 4096

// ---------------------------------------------------------------------------
// Scratch (allocation-free: device globals)
// ---------------------------------------------------------------------------
__device__ __nv_bfloat16 g_xhi[ROWS * DM], g_xlo[ROWS * DM];
__device__ __nv_bfloat16 g_wq_hi[DM * DM], g_wq_lo[DM * DM];
__device__ __nv_bfloat16 g_wk_hi[DM * DM], g_wk_lo[DM * DM];
__device__ __nv_bfloat16 g_wv_hi[DM * DM], g_wv_lo[DM * DM];
__device__ __nv_bfloat16 g_wo_hi[DM * DM], g_wo_lo[DM * DM];
__device__ __nv_bfloat16 g_qhi[BH * S_ * DK], g_qlo[BH * S_ * DK];
__device__ __nv_bfloat16 g_khi[BH * S_ * DK], g_klo[BH * S_ * DK];
__device__ __nv_bfloat16 g_vhi[BH * S_ * DK], g_vlo[BH * S_ * DK];
__device__ __nv_bfloat16 g_cxhi[ROWS * DM], g_cxlo[ROWS * DM];

// ---------------------------------------------------------------------------
// Helpers
// ---------------------------------------------------------------------------
__device__ __forceinline__ uint32_t smem_to_u32(const void* p) {
    uint32_t a;
    asm("{ .reg .u64 t; cvta.to.shared.u64 t, %1; cvt.u32.u64 %0, t; }"
        : "=r"(a) : "l"(p));
    return a;
}
__device__ __forceinline__ void mma16816(float* c, const uint32_t* a, const uint32_t* b) {
    asm volatile("mma.sync.aligned.m16n8k16.row.col.f32.bf16.bf16.f32 "
        "{%0,%1,%2,%3}, {%4,%5,%6,%7}, {%8,%9}, {%0,%1,%2,%3};"
        : "+f"(c[0]), "+f"(c[1]), "+f"(c[2]), "+f"(c[3])
        : "r"(a[0]), "r"(a[1]), "r"(a[2]), "r"(a[3]), "r"(b[0]), "r"(b[1]));
}
__device__ __forceinline__ void ldsm_x4(uint32_t* r, uint32_t a) {
    asm volatile("ldmatrix.sync.aligned.m8n8.x4.shared.b16 {%0,%1,%2,%3}, [%4];"
        : "=r"(r[0]), "=r"(r[1]), "=r"(r[2]), "=r"(r[3]) : "r"(a));
}
__device__ __forceinline__ void ldsm_x4_t(uint32_t* r, uint32_t a) {
    asm volatile("ldmatrix.sync.aligned.m8n8.x4.trans.shared.b16 {%0,%1,%2,%3}, [%4];"
        : "=r"(r[0]), "=r"(r[1]), "=r"(r[2]), "=r"(r[3]) : "r"(a));
}
__device__ __forceinline__ void cp16(uint32_t d, const void* s) {
    asm volatile("cp.async.cg.shared.global [%0], [%1], 16;" :: "r"(d), "l"(s));
}
#define CP_COMMIT asm volatile("cp.async.commit_group;" ::: "memory")
#define CP_WAIT1  asm volatile("cp.async.wait_group 1;" ::: "memory")
#define CP_WAIT0  asm volatile("cp.async.wait_group 0;" ::: "memory")

__device__ __forceinline__ uint32_t packbf(float lo, float hi) {
    uint32_t r;
    asm("cvt.rn.bf16x2.f32 %0, %1, %2;" : "=r"(r) : "f"(hi), "f"(lo));
    return r;
}
__device__ __forceinline__ float bf16rt(float v) {
    return __bfloat162float(__float2bfloat16(v));
}

// ---------------------------------------------------------------------------
// Prep kernels
// ---------------------------------------------------------------------------
__global__ void prep_x_kernel(const float* __restrict__ x,
                              __nv_bfloat16* __restrict__ hi,
                              __nv_bfloat16* __restrict__ lo, int n)
{
    for (int i = blockIdx.x * blockDim.x + threadIdx.x; i < n;
         i += gridDim.x * blockDim.x) {
        float v = x[i];
        __nv_bfloat16 h = __float2bfloat16(v);
        hi[i] = h;
        lo[i] = __float2bfloat16(v - __bfloat162float(h));
    }
}

__global__ void prep_w_heads_kernel(const float* __restrict__ W,
                                    __nv_bfloat16* __restrict__ hi,
                                    __nv_bfloat16* __restrict__ lo)
{
    __shared__ float tile[32][33];
    int t = threadIdx.x, tx = t & 31, ty = t >> 5;
    int k0 = blockIdx.x * 32, c0 = blockIdx.y * 32, h = blockIdx.z;
    const float* src = W + (size_t)h * DM * DK;
    #pragma unroll
    for (int i = 0; i < 32; i += 8)
        tile[ty + i][tx] = src[(size_t)(k0 + ty + i) * DK + c0 + tx];
    __syncthreads();
    #pragma unroll
    for (int i = 0; i < 32; i += 8) {
        int n = h * 64 + c0 + ty + i;
        float v = tile[tx][ty + i];
        __nv_bfloat16 hh = __float2bfloat16(v);
        hi[(size_t)n * DM + k0 + tx] = hh;
        lo[(size_t)n * DM + k0 + tx] = __float2bfloat16(v - __bfloat162float(hh));
    }
}

__global__ void prep_wo_kernel(const float* __restrict__ W,
                               __nv_bfloat16* __restrict__ hi,
                               __nv_bfloat16* __restrict__ lo)
{
    __shared__ float tile[32][33];
    int t = threadIdx.x, tx = t & 31, ty = t >> 5;
    int k0 = blockIdx.x * 32, n0 = blockIdx.y * 32;
    #pragma unroll
    for (int i = 0; i < 32; i += 8)
        tile[ty + i][tx] = W[(size_t)(k0 + ty + i) * DM + n0 + tx];
    __syncthreads();
    #pragma unroll
    for (int i = 0; i < 32; i += 8) {
        int n = n0 + ty + i;
        float v = tile[tx][ty + i];
        __nv_bfloat16 hh = __float2bfloat16(v);
        hi[(size_t)n * DM + k0 + tx] = hh;
        lo[(size_t)n * DM + k0 + tx] = __float2bfloat16(v - __bfloat162float(hh));
    }
}

// ---------------------------------------------------------------------------
// HMMA bf16-split GEMM (unchanged core). mode 1: fused QKV via blockIdx.z.
// ---------------------------------------------------------------------------
struct QKVPtrs {
    const __nv_bfloat16 *bh0, *bl0, *bh1, *bl1, *bh2, *bl2;
    __nv_bfloat16 *oh0, *ol0, *oh1, *ol1, *oh2, *ol2;
};

#define GBK 32
#define GSTRIDE 40
#define GPLANE (128 * GSTRIDE * 2)      // 10240 B
#define GSTAGE (4 * GPLANE)             // 40960 B
#define GEMM_SMEM (2 * GSTAGE)          // 81920 B

__global__ __launch_bounds__(256) void gemm_mma(
    const __nv_bfloat16* __restrict__ Ahi, const __nv_bfloat16* __restrict__ Alo,
    const __nv_bfloat16* __restrict__ Bhi_p, const __nv_bfloat16* __restrict__ Blo_p,
    float* __restrict__ outf, QKVPtrs p, int mode)
{
    extern __shared__ char smem[];
    const uint32_t sb = smem_to_u32(smem);
    const int t = threadIdx.x, w = t >> 5, ln = t & 31;
    const int wm = (w & 1) * 64, wn = (w >> 1) * 32;
    const int row0 = blockIdx.x * 128, col0 = blockIdx.y * 128;

    const __nv_bfloat16 *Bhi = Bhi_p, *Blo = Blo_p;
    __nv_bfloat16 *outhi = nullptr, *outlo = nullptr;
    float alpha = 1.0f;
    if (mode == 1) {
        int z = blockIdx.z;
        if (z == 0) { Bhi = p.bh0; Blo = p.bl0; outhi = p.oh0; outlo = p.ol0; alpha = 0.125f; }
        else if (z == 1) { Bhi = p.bh1; Blo = p.bl1; outhi = p.oh1; outlo = p.ol1; }
        else { Bhi = p.bh2; Blo = p.bl2; outhi = p.oh2; outlo = p.ol2; }
    }

    const __nv_bfloat16* src[4] = {
        Ahi + (size_t)row0 * DM, Alo + (size_t)row0 * DM,
        Bhi + (size_t)col0 * DM, Blo + (size_t)col0 * DM };

    const int ldr0 = t >> 2, ldseg = t & 3;

    float c[4][4][4] = {};

    {
        #pragma unroll
        for (int pi = 0; pi < 4; pi++)
            #pragma unroll
            for (int j = 0; j < 2; j++) {
                int row = ldr0 + j * 64;
                cp16(sb + pi * GPLANE + row * 80 + ldseg * 16,
                     src[pi] + (size_t)row * DM + ldseg * 8);
            }
        CP_COMMIT;
    }

    for (int kc = 0; kc < DM / GBK; kc++) {
        if (kc + 1 < DM / GBK) {
            int k0 = (kc + 1) * GBK;
            uint32_t stn = sb + ((kc + 1) & 1) * GSTAGE;
            #pragma unroll
            for (int pi = 0; pi < 4; pi++)
                #pragma unroll
                for (int j = 0; j < 2; j++) {
                    int row = ldr0 + j * 64;
                    cp16(stn + pi * GPLANE + row * 80 + ldseg * 16,
                         src[pi] + (size_t)row * DM + k0 + ldseg * 8);
                }
            CP_COMMIT;
            CP_WAIT1;
        } else {
            CP_WAIT0;
        }
        __syncthreads();
        uint32_t st = sb + (kc & 1) * GSTAGE;

        #pragma unroll
        for (int ks = 0; ks < 2; ks++) {
            uint32_t bh[4][2], bl[4][2];
            #pragma unroll
            for (int np = 0; np < 2; np++) {
                uint32_t baddr = st + 2 * GPLANE
                    + (wn + np * 16 + ((ln >> 4) & 1) * 8 + (ln & 7)) * 80
                    + ks * 32 + ((ln >> 3) & 1) * 16;
                uint32_t r[4];
                ldsm_x4(r, baddr);
                bh[2*np][0] = r[0]; bh[2*np][1] = r[1];
                bh[2*np+1][0] = r[2]; bh[2*np+1][1] = r[3];
                ldsm_x4(r, baddr + GPLANE);
                bl[2*np][0] = r[0]; bl[2*np][1] = r[1];
                bl[2*np+1][0] = r[2]; bl[2*np+1][1] = r[3];
            }
            #pragma unroll
            for (int mi = 0; mi < 4; mi++) {
                uint32_t aaddr = st + (wm + mi * 16 + (ln & 15)) * 80
                               + ks * 32 + (ln >> 4) * 16;
                uint32_t ah[4], al[4];
                ldsm_x4(ah, aaddr);
                ldsm_x4(al, aaddr + GPLANE);
                #pragma unroll
                for (int ni = 0; ni < 4; ni++) {
                    mma16816(c[mi][ni], ah, bh[ni]);
                    mma16816(c[mi][ni], ah, bl[ni]);
                    mma16816(c[mi][ni], al, bh[ni]);
                }
            }
        }
        __syncthreads();
    }

    #pragma unroll
    for (int mi = 0; mi < 4; mi++) {
        int r = row0 + wm + mi * 16 + (ln >> 2);
        #pragma unroll
        for (int ni = 0; ni < 4; ni++) {
            int cc = col0 + wn + ni * 8 + 2 * (ln & 3);
            if (mode == 0) {
                *(float2*)&outf[(size_t)r * DM + cc] =
                    make_float2(c[mi][ni][0], c[mi][ni][1]);
                *(float2*)&outf[(size_t)(r + 8) * DM + cc] =
                    make_float2(c[mi][ni][2], c[mi][ni][3]);
            } else {
                int h = cc >> 6, d = cc & 63;
                #pragma unroll
                for (int rr = 0; rr < 2; rr++) {
                    int row = r + rr * 8;
                    int b = row >> 11, s = row & (S_ - 1);
                    size_t idx = ((size_t)((b << 4) + h) * S_ + s) * DK + d;
                    float v0 = c[mi][ni][2 * rr + 0] * alpha;
                    float v1 = c[mi][ni][2 * rr + 1] * alpha;
                    float h0 = bf16rt(v0), h1 = bf16rt(v1);
                    *(uint32_t*)&outhi[idx] = packbf(v0, v1);
                    *(uint32_t*)&outlo[idx] = packbf(v0 - h0, v1 - h1);
                }
            }
        }
    }
}

// ---------------------------------------------------------------------------
// HMMA flash attention v2: 4 warps, warp tile m=32 q-rows x 64 t.
// Scores processed in two 32-t sub-chunks to bound registers.
// grid (S/128, BH), 128 threads, 2 CTAs/SM target.
// ---------------------------------------------------------------------------
#define AT_STRIDE 72                     // padded elems (144 B)
#define AT_PLANE (64 * AT_STRIDE * 2)    // 9216 B
#define AT_STAGE (4 * AT_PLANE)          // 36864 : Khi,Klo,Vhi,Vlo
#define ATT_SMEM (2 * AT_STAGE)          // 73728

__global__ __launch_bounds__(128, 2) void attn_mma()
{
    extern __shared__ char smem[];
    const uint32_t sb = smem_to_u32(smem);
    const int t = threadIdx.x, w = t >> 5, ln = t & 31;
    const int bh = blockIdx.y, q0 = blockIdx.x * 128;
    const size_t hbase = (size_t)bh * S_ * DK;

    // Q fragments: warp covers 32 q rows (2 m16 tiles)
    uint32_t qh[4][8], ql[4][8];
    #pragma unroll
    for (int mi = 0; mi < 2; mi++) {
        int r = q0 + w * 32 + mi * 16 + (ln >> 2);
        int cb = 2 * (ln & 3);
        #pragma unroll
        for (int ks = 0; ks < 4; ks++) {
            int c0 = ks * 16 + cb;
            qh[ks][mi*4+0] = *(const uint32_t*)&g_qhi[hbase + (size_t)r * DK + c0];
            qh[ks][mi*4+1] = *(const uint32_t*)&g_qhi[hbase + (size_t)(r + 8) * DK + c0];
            qh[ks][mi*4+2] = *(const uint32_t*)&g_qhi[hbase + (size_t)r * DK + c0 + 8];
            qh[ks][mi*4+3] = *(const uint32_t*)&g_qhi[hbase + (size_t)(r + 8) * DK + c0 + 8];
            ql[ks][mi*4+0] = *(const uint32_t*)&g_qlo[hbase + (size_t)r * DK + c0];
            ql[ks][mi*4+1] = *(const uint32_t*)&g_qlo[hbase + (size_t)(r + 8) * DK + c0];
            ql[ks][mi*4+2] = *(const uint32_t*)&g_qlo[hbase + (size_t)r * DK + c0 + 8];
            ql[ks][mi*4+3] = *(const uint32_t*)&g_qlo[hbase + (size_t)(r + 8) * DK + c0 + 8];
        }
    }

    float ctx[2][8][4] = {};
    float mx[2][2], ls[2][2];
    #pragma unroll
    for (int i = 0; i < 2; i++) {
        mx[i][0] = -CUDART_INF_F; mx[i][1] = -CUDART_INF_F;
        ls[i][0] = 0.f; ls[i][1] = 0.f;
    }

    const __nv_bfloat16* gsrc[4] = { g_khi + hbase, g_klo + hbase,
                                     g_vhi + hbase, g_vlo + hbase };
    // 128 threads: 16 rows x 8 segs per pass, 4 passes cover 64 rows
    const int krow = t >> 3, kseg = t & 7;

    {
        #pragma unroll
        for (int pi = 0; pi < 4; pi++)
            #pragma unroll
            for (int j = 0; j < 4; j++) {
                int row = krow + j * 16;
                cp16(sb + pi * AT_PLANE + row * 144 + kseg * 16,
                     gsrc[pi] + (size_t)row * DK + kseg * 8);
            }
        CP_COMMIT;
    }

    for (int it = 0; it < S_ / 64; it++) {
        if (it + 1 < S_ / 64) {
            uint32_t stn = sb + ((it + 1) & 1) * AT_STAGE;
            #pragma unroll
            for (int pi = 0; pi < 4; pi++)
                #pragma unroll
                for (int j = 0; j < 4; j++) {
                    int row = krow + j * 16;
                    cp16(stn + pi * AT_PLANE + row * 144 + kseg * 16,
                         gsrc[pi] + (size_t)((it + 1) * 64 + row) * DK + kseg * 8);
                }
            CP_COMMIT;
            CP_WAIT1;
        } else {
            CP_WAIT0;
        }
        __syncthreads();
        uint32_t st = sb + (it & 1) * AT_STAGE;

        #pragma unroll
        for (int half = 0; half < 2; half++) {
            // ---- scores for 32-t sub-chunk ----
            float sc[2][4][4] = {};
            #pragma unroll
            for (int ks = 0; ks < 4; ks++) {
                #pragma unroll
                for (int np = 0; np < 2; np++) {
                    uint32_t baddr = st
                        + (half * 32 + np * 16 + ((ln >> 4) & 1) * 8 + (ln & 7)) * 144
                        + ks * 32 + ((ln >> 3) & 1) * 16;
                    uint32_t rh[4], rl[4];
                    ldsm_x4(rh, baddr);
                    ldsm_x4(rl, baddr + AT_PLANE);
                    uint32_t b0[2] = { rh[0], rh[1] }, b1[2] = { rh[2], rh[3] };
                    uint32_t l0[2] = { rl[0], rl[1] }, l1[2] = { rl[2], rl[3] };
                    #pragma unroll
                    for (int mi = 0; mi < 2; mi++) {
                        mma16816(sc[mi][2*np],   qh[ks] + mi*4, b0);
                        mma16816(sc[mi][2*np],   qh[ks] + mi*4, l0);
                        mma16816(sc[mi][2*np],   ql[ks] + mi*4, b0);
                        mma16816(sc[mi][2*np+1], qh[ks] + mi*4, b1);
                        mma16816(sc[mi][2*np+1], qh[ks] + mi*4, l1);
                        mma16816(sc[mi][2*np+1], ql[ks] + mi*4, b1);
                    }
                }
            }

            // ---- online softmax per m16 tile ----
            #pragma unroll
            for (int mi = 0; mi < 2; mi++) {
                float rm0 = -CUDART_INF_F, rm1 = -CUDART_INF_F;
                #pragma unroll
                for (int nj = 0; nj < 4; nj++) {
                    rm0 = fmaxf(rm0, fmaxf(sc[mi][nj][0], sc[mi][nj][1]));
                    rm1 = fmaxf(rm1, fmaxf(sc[mi][nj][2], sc[mi][nj][3]));
                }
                rm0 = fmaxf(rm0, __shfl_xor_sync(0xffffffffu, rm0, 1));
                rm0 = fmaxf(rm0, __shfl_xor_sync(0xffffffffu, rm0, 2));
                rm1 = fmaxf(rm1, __shfl_xor_sync(0xffffffffu, rm1, 1));
                rm1 = fmaxf(rm1, __shfl_xor_sync(0xffffffffu, rm1, 2));
                float mn0 = fmaxf(mx[mi][0], rm0), mn1 = fmaxf(mx[mi][1], rm1);
                float a0 = __expf(mx[mi][0] - mn0), a1 = __expf(mx[mi][1] - mn1);
                mx[mi][0] = mn0; mx[mi][1] = mn1;
                float rs0 = 0.f, rs1 = 0.f;
                #pragma unroll
                for (int nj = 0; nj < 4; nj++) {
                    sc[mi][nj][0] = __expf(sc[mi][nj][0] - mn0);
                    sc[mi][nj][1] = __expf(sc[mi][nj][1] - mn0);
                    sc[mi][nj][2] = __expf(sc[mi][nj][2] - mn1);
                    sc[mi][nj][3] = __expf(sc[mi][nj][3] - mn1);
                    rs0 += sc[mi][nj][0] + sc[mi][nj][1];
                    rs1 += sc[mi][nj][2] + sc[mi][nj][3];
                }
                rs0 += __shfl_xor_sync(0xffffffffu, rs0, 1);
                rs0 += __shfl_xor_sync(0xffffffffu, rs0, 2);
                rs1 += __shfl_xor_sync(0xffffffffu, rs1, 1);
                rs1 += __shfl_xor_sync(0xffffffffu, rs1, 2);
                ls[mi][0] = ls[mi][0] * a0 + rs0;
                ls[mi][1] = ls[mi][1] * a1 + rs1;
                #pragma unroll
                for (int vt = 0; vt < 8; vt++) {
                    ctx[mi][vt][0] *= a0; ctx[mi][vt][1] *= a0;
                    ctx[mi][vt][2] *= a1; ctx[mi][vt][3] *= a1;
                }
            }

            // ---- P fragments by register reinterleave (2 k16 steps) ----
            uint32_t ph[2][2][4], pl[2][2][4];
            #pragma unroll
            for (int mi = 0; mi < 2; mi++)
                #pragma unroll
                for (int kk = 0; kk < 2; kk++)
                    #pragma unroll
                    for (int e = 0; e < 4; e++) {
                        int tile = 2 * kk + (e >> 1);
                        int o = (e & 1) * 2;
                        float x = sc[mi][tile][o], y = sc[mi][tile][o + 1];
                        ph[mi][kk][e] = packbf(x, y);
                        pl[mi][kk][e] = packbf(x - bf16rt(x), y - bf16rt(y));
                    }

            // ---- ctx += P * V for this 32-t sub-chunk ----
            #pragma unroll
            for (int kk = 0; kk < 2; kk++) {
                #pragma unroll
                for (int vp = 0; vp < 4; vp++) {
                    uint32_t vaddr = st + 2 * AT_PLANE
                        + (half * 32 + kk * 16 + ((ln >> 3) & 1) * 8 + (ln & 7)) * 144
                        + vp * 32 + ((ln >> 4) & 1) * 16;
                    uint32_t rh[4], rl[4];
                    ldsm_x4_t(rh, vaddr);
                    ldsm_x4_t(rl, vaddr + AT_PLANE);
                    uint32_t b0[2] = { rh[0], rh[1] }, b1[2] = { rh[2], rh[3] };
                    uint32_t l0[2] = { rl[0], rl[1] }, l1[2] = { rl[2], rl[3] };
                    #pragma unroll
                    for (int mi = 0; mi < 2; mi++) {
                        mma16816(ctx[mi][2*vp],   ph[mi][kk], b0);
                        mma16816(ctx[mi][2*vp],   ph[mi][kk], l0);
                        mma16816(ctx[mi][2*vp],   pl[mi][kk], b0);
                        mma16816(ctx[mi][2*vp+1], ph[mi][kk], b1);
                        mma16816(ctx[mi][2*vp+1], ph[mi][kk], l1);
                        mma16816(ctx[mi][2*vp+1], pl[mi][kk], b1);
                    }
                }
            }
        }
        __syncthreads();
    }

    // ---- epilogue ----
    const int b = bh >> 4, h = bh & 15;
    #pragma unroll
    for (int mi = 0; mi < 2; mi++) {
        float inv0 = 1.f / ls[mi][0], inv1 = 1.f / ls[mi][1];
        int r = q0 + w * 32 + mi * 16 + (ln >> 2);
        size_t ob0 = ((size_t)(b * S_ + r)) * DM + h * 64;
        size_t ob1 = ob0 + (size_t)8 * DM;
        #pragma unroll
        for (int vt = 0; vt < 8; vt++) {
            int cc = vt * 8 + 2 * (ln & 3);
            float v0 = ctx[mi][vt][0] * inv0, v1 = ctx[mi][vt][1] * inv0;
            float v2 = ctx[mi][vt][2] * inv1, v3 = ctx[mi][vt][3] * inv1;
            *(uint32_t*)&g_cxhi[ob0 + cc] = packbf(v0, v1);
            *(uint32_t*)&g_cxlo[ob0 + cc] = packbf(v0 - bf16rt(v0), v1 - bf16rt(v1));
            *(uint32_t*)&g_cxhi[ob1 + cc] = packbf(v2, v3);
            *(uint32_t*)&g_cxlo[ob1 + cc] = packbf(v2 - bf16rt(v2), v3 - bf16rt(v3));
        }
    }
}

// ---------------------------------------------------------------------------
// Launch. Input order per metadata: x, Wk, Wq, Wv, Wo
// ---------------------------------------------------------------------------
extern "C" void kernel_launch(void* const* d_in, const int* in_sizes, int n_in,
                              void* d_out, int out_size)
{
    const float* x  = (const float*)d_in[0];
    const float* Wk = (const float*)d_in[1];
    const float* Wq = (const float*)d_in[2];
    const float* Wv = (const float*)d_in[3];
    const float* Wo = (const float*)d_in[4];
    float* out = (float*)d_out;

    cudaFuncSetAttribute(gemm_mma,
                         cudaFuncAttributeMaxDynamicSharedMemorySize, GEMM_SMEM);
    cudaFuncSetAttribute(attn_mma,
                         cudaFuncAttributeMaxDynamicSharedMemorySize, ATT_SMEM);

    __nv_bfloat16 *xhi, *xlo, *wqh, *wql, *wkh, *wkl, *wvh, *wvl, *woh, *wol;
    __nv_bfloat16 *qhi, *qlo, *khi, *klo, *vhi, *vlo, *cxh, *cxl;
    cudaGetSymbolAddress((void**)&xhi, g_xhi);
    cudaGetSymbolAddress((void**)&xlo, g_xlo);
    cudaGetSymbolAddress((void**)&wqh, g_wq_hi);
    cudaGetSymbolAddress((void**)&wql, g_wq_lo);
    cudaGetSymbolAddress((void**)&wkh, g_wk_hi);
    cudaGetSymbolAddress((void**)&wkl, g_wk_lo);
    cudaGetSymbolAddress((void**)&wvh, g_wv_hi);
    cudaGetSymbolAddress((void**)&wvl, g_wv_lo);
    cudaGetSymbolAddress((void**)&woh, g_wo_hi);
    cudaGetSymbolAddress((void**)&wol, g_wo_lo);
    cudaGetSymbolAddress((void**)&qhi, g_qhi);
    cudaGetSymbolAddress((void**)&qlo, g_qlo);
    cudaGetSymbolAddress((void**)&khi, g_khi);
    cudaGetSymbolAddress((void**)&klo, g_klo);
    cudaGetSymbolAddress((void**)&vhi, g_vhi);
    cudaGetSymbolAddress((void**)&vlo, g_vlo);
    cudaGetSymbolAddress((void**)&cxh, g_cxhi);
    cudaGetSymbolAddress((void**)&cxl, g_cxlo);

    prep_x_kernel<<<1024, 256>>>(x, xhi, xlo, ROWS * DM);
    prep_w_heads_kernel<<<dim3(32, 2, 16), 256>>>(Wq, wqh, wql);
    prep_w_heads_kernel<<<dim3(32, 2, 16), 256>>>(Wk, wkh, wkl);
    prep_w_heads_kernel<<<dim3(32, 2, 16), 256>>>(Wv, wvh, wvl);
    prep_wo_kernel<<<dim3(32, 32), 256>>>(Wo, woh, wol);

    QKVPtrs p;
    p.bh0 = wqh; p.bl0 = wql; p.oh0 = qhi; p.ol0 = qlo;
    p.bh1 = wkh; p.bl1 = wkl; p.oh1 = khi; p.ol1 = klo;
    p.bh2 = wvh; p.bl2 = wvl; p.oh2 = vhi; p.ol2 = vlo;

    gemm_mma<<<dim3(32, 8, 3), 256, GEMM_SMEM>>>(xhi, xlo, nullptr, nullptr,
                                                 nullptr, p, 1);

    attn_mma<<<dim3(S_ / 128, BH), 128, ATT_SMEM>>>();

    QKVPtrs dummy = {};
    gemm_mma<<<dim3(32, 8), 256, GEMM_SMEM>>>(cxh, cxl, woh, wol,
                                              out, dummy, 0);
}

// round 7
// speedup vs baseline: 3.3624x; 1.0789x over previous
#include <cuda_runtime.h>
#include <cuda_bf16.h>
#include <cuda_fp16.h>
#include <math_constants.h>
#include <cstdint>

#define B_  2
#define S_  2048
#define DM  1024
#define DK  64
#define H_  16
#define BH  (B_ * H_)
#define ROWS (B_ * S_)          // 4096

// ---------------------------------------------------------------------------
// Scratch (allocation-free: device globals)
// ---------------------------------------------------------------------------
__device__ __nv_bfloat16 g_xhi[ROWS * DM], g_xlo[ROWS * DM];
__device__ __nv_bfloat16 g_wq_hi[DM * DM], g_wq_lo[DM * DM];
__device__ __nv_bfloat16 g_wk_hi[DM * DM], g_wk_lo[DM * DM];
__device__ __nv_bfloat16 g_wv_hi[DM * DM], g_wv_lo[DM * DM];
__device__ __nv_bfloat16 g_wo_hi[DM * DM], g_wo_lo[DM * DM];
__device__ __half g_qhi[BH * S_ * DK], g_qlo[BH * S_ * DK];
__device__ __half g_khi[BH * S_ * DK];
__device__ __half g_vhi[BH * S_ * DK], g_vlo[BH * S_ * DK];
__device__ __nv_bfloat16 g_cxhi[ROWS * DM], g_cxlo[ROWS * DM];

// Q pre-scale: (1/sqrt(64)) * log2(e)  -> softmax computed in base-2
#define Q_ALPHA 0.18033688011112042f

// ---------------------------------------------------------------------------
// Helpers
// ---------------------------------------------------------------------------
__device__ __forceinline__ uint32_t smem_to_u32(const void* p) {
    uint32_t a;
    asm("{ .reg .u64 t; cvta.to.shared.u64 t, %1; cvt.u32.u64 %0, t; }"
        : "=r"(a) : "l"(p));
    return a;
}
// bf16 mma
__device__ __forceinline__ void mma16816(float* c, const uint32_t* a, const uint32_t* b) {
    asm volatile("mma.sync.aligned.m16n8k16.row.col.f32.bf16.bf16.f32 "
        "{%0,%1,%2,%3}, {%4,%5,%6,%7}, {%8,%9}, {%0,%1,%2,%3};"
        : "+f"(c[0]), "+f"(c[1]), "+f"(c[2]), "+f"(c[3])
        : "r"(a[0]), "r"(a[1]), "r"(a[2]), "r"(a[3]), "r"(b[0]), "r"(b[1]));
}
// fp16 mma
__device__ __forceinline__ void mma16816h(float* c, const uint32_t* a, const uint32_t* b) {
    asm volatile("mma.sync.aligned.m16n8k16.row.col.f32.f16.f16.f32 "
        "{%0,%1,%2,%3}, {%4,%5,%6,%7}, {%8,%9}, {%0,%1,%2,%3};"
        : "+f"(c[0]), "+f"(c[1]), "+f"(c[2]), "+f"(c[3])
        : "r"(a[0]), "r"(a[1]), "r"(a[2]), "r"(a[3]), "r"(b[0]), "r"(b[1]));
}
__device__ __forceinline__ void ldsm_x4(uint32_t* r, uint32_t a) {
    asm volatile("ldmatrix.sync.aligned.m8n8.x4.shared.b16 {%0,%1,%2,%3}, [%4];"
        : "=r"(r[0]), "=r"(r[1]), "=r"(r[2]), "=r"(r[3]) : "r"(a));
}
__device__ __forceinline__ void ldsm_x4_t(uint32_t* r, uint32_t a) {
    asm volatile("ldmatrix.sync.aligned.m8n8.x4.trans.shared.b16 {%0,%1,%2,%3}, [%4];"
        : "=r"(r[0]), "=r"(r[1]), "=r"(r[2]), "=r"(r[3]) : "r"(a));
}
__device__ __forceinline__ void cp16(uint32_t d, const void* s) {
    asm volatile("cp.async.cg.shared.global [%0], [%1], 16;" :: "r"(d), "l"(s));
}
#define CP_COMMIT asm volatile("cp.async.commit_group;" ::: "memory")
#define CP_WAIT1  asm volatile("cp.async.wait_group 1;" ::: "memory")
#define CP_WAIT0  asm volatile("cp.async.wait_group 0;" ::: "memory")

// pack two floats as bf16x2 (first arg -> low half)
__device__ __forceinline__ uint32_t packbf(float lo, float hi) {
    uint32_t r;
    asm("cvt.rn.bf16x2.f32 %0, %1, %2;" : "=r"(r) : "f"(hi), "f"(lo));
    return r;
}
// pack two floats as f16x2 (first arg -> low half)
__device__ __forceinline__ uint32_t packh(float lo, float hi) {
    uint32_t r;
    asm("cvt.rn.f16x2.f32 %0, %1, %2;" : "=r"(r) : "f"(hi), "f"(lo));
    return r;
}

// ---------------------------------------------------------------------------
// Prep kernels (fp32 -> bf16 hi/lo)
// ---------------------------------------------------------------------------
__global__ void prep_x_kernel(const float* __restrict__ x,
                              __nv_bfloat16* __restrict__ hi,
                              __nv_bfloat16* __restrict__ lo, int n)
{
    for (int i = blockIdx.x * blockDim.x + threadIdx.x; i < n;
         i += gridDim.x * blockDim.x) {
        float v = x[i];
        __nv_bfloat16 h = __float2bfloat16(v);
        hi[i] = h;
        lo[i] = __float2bfloat16(v - __bfloat162float(h));
    }
}

__global__ void prep_w_heads_kernel(const float* __restrict__ W,
                                    __nv_bfloat16* __restrict__ hi,
                                    __nv_bfloat16* __restrict__ lo)
{
    __shared__ float tile[32][33];
    int t = threadIdx.x, tx = t & 31, ty = t >> 5;
    int k0 = blockIdx.x * 32, c0 = blockIdx.y * 32, h = blockIdx.z;
    const float* src = W + (size_t)h * DM * DK;
    #pragma unroll
    for (int i = 0; i < 32; i += 8)
        tile[ty + i][tx] = src[(size_t)(k0 + ty + i) * DK + c0 + tx];
    __syncthreads();
    #pragma unroll
    for (int i = 0; i < 32; i += 8) {
        int n = h * 64 + c0 + ty + i;
        float v = tile[tx][ty + i];
        __nv_bfloat16 hh = __float2bfloat16(v);
        hi[(size_t)n * DM + k0 + tx] = hh;
        lo[(size_t)n * DM + k0 + tx] = __float2bfloat16(v - __bfloat162float(hh));
    }
}

__global__ void prep_wo_kernel(const float* __restrict__ W,
                               __nv_bfloat16* __restrict__ hi,
                               __nv_bfloat16* __restrict__ lo)
{
    __shared__ float tile[32][33];
    int t = threadIdx.x, tx = t & 31, ty = t >> 5;
    int k0 = blockIdx.x * 32, n0 = blockIdx.y * 32;
    #pragma unroll
    for (int i = 0; i < 32; i += 8)
        tile[ty + i][tx] = W[(size_t)(k0 + ty + i) * DM + n0 + tx];
    __syncthreads();
    #pragma unroll
    for (int i = 0; i < 32; i += 8) {
        int n = n0 + ty + i;
        float v = tile[tx][ty + i];
        __nv_bfloat16 hh = __float2bfloat16(v);
        hi[(size_t)n * DM + k0 + tx] = hh;
        lo[(size_t)n * DM + k0 + tx] = __float2bfloat16(v - __bfloat162float(hh));
    }
}

// ---------------------------------------------------------------------------
// HMMA bf16-split GEMM. mode 1 (fused QKV, blockIdx.z selects proj):
//   z=0: Q -> fp16 hi/lo, scaled by Q_ALPHA
//   z=1: K -> fp16 hi only
//   z=2: V -> fp16 hi/lo
// mode 0: fp32 row-major out (output projection)
// ---------------------------------------------------------------------------
struct QKVPtrs {
    const __nv_bfloat16 *bh0, *bl0, *bh1, *bl1, *bh2, *bl2;
    __half *oh0, *ol0, *oh1, *oh2, *ol2;
};

#define GBK 32
#define GSTRIDE 40
#define GPLANE (128 * GSTRIDE * 2)      // 10240 B
#define GSTAGE (4 * GPLANE)             // 40960 B
#define GEMM_SMEM (2 * GSTAGE)          // 81920 B

__global__ __launch_bounds__(256) void gemm_mma(
    const __nv_bfloat16* __restrict__ Ahi, const __nv_bfloat16* __restrict__ Alo,
    const __nv_bfloat16* __restrict__ Bhi_p, const __nv_bfloat16* __restrict__ Blo_p,
    float* __restrict__ outf, QKVPtrs p, int mode)
{
    extern __shared__ char smem[];
    const uint32_t sb = smem_to_u32(smem);
    const int t = threadIdx.x, w = t >> 5, ln = t & 31;
    const int wm = (w & 1) * 64, wn = (w >> 1) * 32;
    const int row0 = blockIdx.x * 128, col0 = blockIdx.y * 128;

    const __nv_bfloat16 *Bhi = Bhi_p, *Blo = Blo_p;
    __half *outhi = nullptr, *outlo = nullptr;
    float alpha = 1.0f;
    int z = -1;
    if (mode == 1) {
        z = blockIdx.z;
        if (z == 0) { Bhi = p.bh0; Blo = p.bl0; outhi = p.oh0; outlo = p.ol0; alpha = Q_ALPHA; }
        else if (z == 1) { Bhi = p.bh1; Blo = p.bl1; outhi = p.oh1; }
        else { Bhi = p.bh2; Blo = p.bl2; outhi = p.oh2; outlo = p.ol2; }
    }

    const __nv_bfloat16* src[4] = {
        Ahi + (size_t)row0 * DM, Alo + (size_t)row0 * DM,
        Bhi + (size_t)col0 * DM, Blo + (size_t)col0 * DM };

    const int ldr0 = t >> 2, ldseg = t & 3;

    float c[4][4][4] = {};

    {
        #pragma unroll
        for (int pi = 0; pi < 4; pi++)
            #pragma unroll
            for (int j = 0; j < 2; j++) {
                int row = ldr0 + j * 64;
                cp16(sb + pi * GPLANE + row * 80 + ldseg * 16,
                     src[pi] + (size_t)row * DM + ldseg * 8);
            }
        CP_COMMIT;
    }

    for (int kc = 0; kc < DM / GBK; kc++) {
        if (kc + 1 < DM / GBK) {
            int k0 = (kc + 1) * GBK;
            uint32_t stn = sb + ((kc + 1) & 1) * GSTAGE;
            #pragma unroll
            for (int pi = 0; pi < 4; pi++)
                #pragma unroll
                for (int j = 0; j < 2; j++) {
                    int row = ldr0 + j * 64;
                    cp16(stn + pi * GPLANE + row * 80 + ldseg * 16,
                         src[pi] + (size_t)row * DM + k0 + ldseg * 8);
                }
            CP_COMMIT;
            CP_WAIT1;
        } else {
            CP_WAIT0;
        }
        __syncthreads();
        uint32_t st = sb + (kc & 1) * GSTAGE;

        #pragma unroll
        for (int ks = 0; ks < 2; ks++) {
            uint32_t bh[4][2], bl[4][2];
            #pragma unroll
            for (int np = 0; np < 2; np++) {
                uint32_t baddr = st + 2 * GPLANE
                    + (wn + np * 16 + ((ln >> 4) & 1) * 8 + (ln & 7)) * 80
                    + ks * 32 + ((ln >> 3) & 1) * 16;
                uint32_t r[4];
                ldsm_x4(r, baddr);
                bh[2*np][0] = r[0]; bh[2*np][1] = r[1];
                bh[2*np+1][0] = r[2]; bh[2*np+1][1] = r[3];
                ldsm_x4(r, baddr + GPLANE);
                bl[2*np][0] = r[0]; bl[2*np][1] = r[1];
                bl[2*np+1][0] = r[2]; bl[2*np+1][1] = r[3];
            }
            #pragma unroll
            for (int mi = 0; mi < 4; mi++) {
                uint32_t aaddr = st + (wm + mi * 16 + (ln & 15)) * 80
                               + ks * 32 + (ln >> 4) * 16;
                uint32_t ah[4], al[4];
                ldsm_x4(ah, aaddr);
                ldsm_x4(al, aaddr + GPLANE);
                #pragma unroll
                for (int ni = 0; ni < 4; ni++) {
                    mma16816(c[mi][ni], ah, bh[ni]);
                    mma16816(c[mi][ni], ah, bl[ni]);
                    mma16816(c[mi][ni], al, bh[ni]);
                }
            }
        }
        __syncthreads();
    }

    #pragma unroll
    for (int mi = 0; mi < 4; mi++) {
        int r = row0 + wm + mi * 16 + (ln >> 2);
        #pragma unroll
        for (int ni = 0; ni < 4; ni++) {
            int cc = col0 + wn + ni * 8 + 2 * (ln & 3);
            if (mode == 0) {
                *(float2*)&outf[(size_t)r * DM + cc] =
                    make_float2(c[mi][ni][0], c[mi][ni][1]);
                *(float2*)&outf[(size_t)(r + 8) * DM + cc] =
                    make_float2(c[mi][ni][2], c[mi][ni][3]);
            } else {
                int h = cc >> 6, d = cc & 63;
                #pragma unroll
                for (int rr = 0; rr < 2; rr++) {
                    int row = r + rr * 8;
                    int b = row >> 11, s = row & (S_ - 1);
                    size_t idx = ((size_t)((b << 4) + h) * S_ + s) * DK + d;
                    float v0 = c[mi][ni][2 * rr + 0] * alpha;
                    float v1 = c[mi][ni][2 * rr + 1] * alpha;
                    uint32_t ph = packh(v0, v1);
                    *(uint32_t*)&outhi[idx] = ph;
                    if (z != 1) {
                        __half2 h2 = *(__half2*)&ph;
                        float r0 = v0 - __half2float(__low2half(h2));
                        float r1 = v1 - __half2float(__high2half(h2));
                        *(uint32_t*)&outlo[idx] = packh(r0, r1);
                    }
                }
            }
        }
    }
}

// ---------------------------------------------------------------------------
// FP16 flash attention: 4 warps, warp tile m=32 x 64 t, 2 CTAs/SM.
// scores = qh*kh + ql*kh (2 products, K single fp16 plane);
// PV = 3-product fp16. Softmax in base-2 (Q pre-scaled by log2 e).
// ---------------------------------------------------------------------------
#define AT_STRIDE 72                     // padded elems (144 B)
#define AT_PLANE (64 * AT_STRIDE * 2)    // 9216 B
#define AT_STAGE (3 * AT_PLANE)          // 27648 : Kh, Vh, Vl
#define ATT_SMEM (2 * AT_STAGE)          // 55296

__global__ __launch_bounds__(128, 2) void attn_mma()
{
    extern __shared__ char smem[];
    const uint32_t sb = smem_to_u32(smem);
    const int t = threadIdx.x, w = t >> 5, ln = t & 31;
    const int bh = blockIdx.y, q0 = blockIdx.x * 128;
    const size_t hbase = (size_t)bh * S_ * DK;

    // Q fragments (fp16, pre-scaled by Q_ALPHA)
    uint32_t qh[4][8], ql[4][8];
    #pragma unroll
    for (int mi = 0; mi < 2; mi++) {
        int r = q0 + w * 32 + mi * 16 + (ln >> 2);
        int cb = 2 * (ln & 3);
        #pragma unroll
        for (int ks = 0; ks < 4; ks++) {
            int c0 = ks * 16 + cb;
            qh[ks][mi*4+0] = *(const uint32_t*)&g_qhi[hbase + (size_t)r * DK + c0];
            qh[ks][mi*4+1] = *(const uint32_t*)&g_qhi[hbase + (size_t)(r + 8) * DK + c0];
            qh[ks][mi*4+2] = *(const uint32_t*)&g_qhi[hbase + (size_t)r * DK + c0 + 8];
            qh[ks][mi*4+3] = *(const uint32_t*)&g_qhi[hbase + (size_t)(r + 8) * DK + c0 + 8];
            ql[ks][mi*4+0] = *(const uint32_t*)&g_qlo[hbase + (size_t)r * DK + c0];
            ql[ks][mi*4+1] = *(const uint32_t*)&g_qlo[hbase + (size_t)(r + 8) * DK + c0];
            ql[ks][mi*4+2] = *(const uint32_t*)&g_qlo[hbase + (size_t)r * DK + c0 + 8];
            ql[ks][mi*4+3] = *(const uint32_t*)&g_qlo[hbase + (size_t)(r + 8) * DK + c0 + 8];
        }
    }

    float ctx[2][8][4] = {};
    float mx[2][2], ls[2][2];
    #pragma unroll
    for (int i = 0; i < 2; i++) {
        mx[i][0] = -CUDART_INF_F; mx[i][1] = -CUDART_INF_F;
        ls[i][0] = 0.f; ls[i][1] = 0.f;
    }

    const __half* gsrc[3] = { g_khi + hbase, g_vhi + hbase, g_vlo + hbase };
    const int krow = t >> 3, kseg = t & 7;

    {
        #pragma unroll
        for (int pi = 0; pi < 3; pi++)
            #pragma unroll
            for (int j = 0; j < 4; j++) {
                int row = krow + j * 16;
                cp16(sb + pi * AT_PLANE + row * 144 + kseg * 16,
                     gsrc[pi] + (size_t)row * DK + kseg * 8);
            }
        CP_COMMIT;
    }

    for (int it = 0; it < S_ / 64; it++) {
        if (it + 1 < S_ / 64) {
            uint32_t stn = sb + ((it + 1) & 1) * AT_STAGE;
            #pragma unroll
            for (int pi = 0; pi < 3; pi++)
                #pragma unroll
                for (int j = 0; j < 4; j++) {
                    int row = krow + j * 16;
                    cp16(stn + pi * AT_PLANE + row * 144 + kseg * 16,
                         gsrc[pi] + (size_t)((it + 1) * 64 + row) * DK + kseg * 8);
                }
            CP_COMMIT;
            CP_WAIT1;
        } else {
            CP_WAIT0;
        }
        __syncthreads();
        uint32_t st = sb + (it & 1) * AT_STAGE;

        #pragma unroll
        for (int half = 0; half < 2; half++) {
            // ---- scores: 2-product fp16 (qh*kh + ql*kh) ----
            float sc[2][4][4] = {};
            #pragma unroll
            for (int ks = 0; ks < 4; ks++) {
                #pragma unroll
                for (int np = 0; np < 2; np++) {
                    uint32_t baddr = st
                        + (half * 32 + np * 16 + ((ln >> 4) & 1) * 8 + (ln & 7)) * 144
                        + ks * 32 + ((ln >> 3) & 1) * 16;
                    uint32_t rh[4];
                    ldsm_x4(rh, baddr);
                    uint32_t b0[2] = { rh[0], rh[1] }, b1[2] = { rh[2], rh[3] };
                    #pragma unroll
                    for (int mi = 0; mi < 2; mi++) {
                        mma16816h(sc[mi][2*np],   qh[ks] + mi*4, b0);
                        mma16816h(sc[mi][2*np],   ql[ks] + mi*4, b0);
                        mma16816h(sc[mi][2*np+1], qh[ks] + mi*4, b1);
                        mma16816h(sc[mi][2*np+1], ql[ks] + mi*4, b1);
                    }
                }
            }

            // ---- online softmax (base-2) ----
            #pragma unroll
            for (int mi = 0; mi < 2; mi++) {
                float rm0 = -CUDART_INF_F, rm1 = -CUDART_INF_F;
                #pragma unroll
                for (int nj = 0; nj < 4; nj++) {
                    rm0 = fmaxf(rm0, fmaxf(sc[mi][nj][0], sc[mi][nj][1]));
                    rm1 = fmaxf(rm1, fmaxf(sc[mi][nj][2], sc[mi][nj][3]));
                }
                rm0 = fmaxf(rm0, __shfl_xor_sync(0xffffffffu, rm0, 1));
                rm0 = fmaxf(rm0, __shfl_xor_sync(0xffffffffu, rm0, 2));
                rm1 = fmaxf(rm1, __shfl_xor_sync(0xffffffffu, rm1, 1));
                rm1 = fmaxf(rm1, __shfl_xor_sync(0xffffffffu, rm1, 2));
                float mn0 = fmaxf(mx[mi][0], rm0), mn1 = fmaxf(mx[mi][1], rm1);
                float a0 = exp2f(mx[mi][0] - mn0), a1 = exp2f(mx[mi][1] - mn1);
                mx[mi][0] = mn0; mx[mi][1] = mn1;
                float rs0 = 0.f, rs1 = 0.f;
                #pragma unroll
                for (int nj = 0; nj < 4; nj++) {
                    sc[mi][nj][0] = exp2f(sc[mi][nj][0] - mn0);
                    sc[mi][nj][1] = exp2f(sc[mi][nj][1] - mn0);
                    sc[mi][nj][2] = exp2f(sc[mi][nj][2] - mn1);
                    sc[mi][nj][3] = exp2f(sc[mi][nj][3] - mn1);
                    rs0 += sc[mi][nj][0] + sc[mi][nj][1];
                    rs1 += sc[mi][nj][2] + sc[mi][nj][3];
                }
                rs0 += __shfl_xor_sync(0xffffffffu, rs0, 1);
                rs0 += __shfl_xor_sync(0xffffffffu, rs0, 2);
                rs1 += __shfl_xor_sync(0xffffffffu, rs1, 1);
                rs1 += __shfl_xor_sync(0xffffffffu, rs1, 2);
                ls[mi][0] = ls[mi][0] * a0 + rs0;
                ls[mi][1] = ls[mi][1] * a1 + rs1;
                #pragma unroll
                for (int vt = 0; vt < 8; vt++) {
                    ctx[mi][vt][0] *= a0; ctx[mi][vt][1] *= a0;
                    ctx[mi][vt][2] *= a1; ctx[mi][vt][3] *= a1;
                }
            }

            // ---- P fragments (fp16 hi/lo) by register reinterleave ----
            uint32_t ph[2][2][4], pl[2][2][4];
            #pragma unroll
            for (int mi = 0; mi < 2; mi++)
                #pragma unroll
                for (int kk = 0; kk < 2; kk++)
                    #pragma unroll
                    for (int e = 0; e < 4; e++) {
                        int tile = 2 * kk + (e >> 1);
                        int o = (e & 1) * 2;
                        float x = sc[mi][tile][o], y = sc[mi][tile][o + 1];
                        uint32_t pp = packh(x, y);
                        ph[mi][kk][e] = pp;
                        __half2 h2 = *(__half2*)&pp;
                        pl[mi][kk][e] = packh(x - __half2float(__low2half(h2)),
                                              y - __half2float(__high2half(h2)));
                    }

            // ---- ctx += P * V (3-product fp16) ----
            #pragma unroll
            for (int kk = 0; kk < 2; kk++) {
                #pragma unroll
                for (int vp = 0; vp < 4; vp++) {
                    uint32_t vaddr = st + 1 * AT_PLANE
                        + (half * 32 + kk * 16 + ((ln >> 3) & 1) * 8 + (ln & 7)) * 144
                        + vp * 32 + ((ln >> 4) & 1) * 16;
                    uint32_t rh[4], rl[4];
                    ldsm_x4_t(rh, vaddr);
                    ldsm_x4_t(rl, vaddr + AT_PLANE);
                    uint32_t b0[2] = { rh[0], rh[1] }, b1[2] = { rh[2], rh[3] };
                    uint32_t l0[2] = { rl[0], rl[1] }, l1[2] = { rl[2], rl[3] };
                    #pragma unroll
                    for (int mi = 0; mi < 2; mi++) {
                        mma16816h(ctx[mi][2*vp],   ph[mi][kk], b0);
                        mma16816h(ctx[mi][2*vp],   ph[mi][kk], l0);
                        mma16816h(ctx[mi][2*vp],   pl[mi][kk], b0);
                        mma16816h(ctx[mi][2*vp+1], ph[mi][kk], b1);
                        mma16816h(ctx[mi][2*vp+1], ph[mi][kk], l1);
                        mma16816h(ctx[mi][2*vp+1], pl[mi][kk], b1);
                    }
                }
            }
        }
        __syncthreads();
    }

    // ---- epilogue: ctx -> bf16 hi/lo (bit-trick residuals) ----
    const int b = bh >> 4, h = bh & 15;
    #pragma unroll
    for (int mi = 0; mi < 2; mi++) {
        float inv0 = 1.f / ls[mi][0], inv1 = 1.f / ls[mi][1];
        int r = q0 + w * 32 + mi * 16 + (ln >> 2);
        size_t ob0 = ((size_t)(b * S_ + r)) * DM + h * 64;
        size_t ob1 = ob0 + (size_t)8 * DM;
        #pragma unroll
        for (int vt = 0; vt < 8; vt++) {
            int cc = vt * 8 + 2 * (ln & 3);
            float v0 = ctx[mi][vt][0] * inv0, v1 = ctx[mi][vt][1] * inv0;
            float v2 = ctx[mi][vt][2] * inv1, v3 = ctx[mi][vt][3] * inv1;
            uint32_t pA = packbf(v0, v1);
            uint32_t pB = packbf(v2, v3);
            *(uint32_t*)&g_cxhi[ob0 + cc] = pA;
            *(uint32_t*)&g_cxhi[ob1 + cc] = pB;
            *(uint32_t*)&g_cxlo[ob0 + cc] =
                packbf(v0 - __uint_as_float(pA << 16),
                       v1 - __uint_as_float(pA & 0xFFFF0000u));
            *(uint32_t*)&g_cxlo[ob1 + cc] =
                packbf(v2 - __uint_as_float(pB << 16),
                       v3 - __uint_as_float(pB & 0xFFFF0000u));
        }
    }
}

// ---------------------------------------------------------------------------
// Launch. Input order per metadata: x, Wk, Wq, Wv, Wo
// ---------------------------------------------------------------------------
extern "C" void kernel_launch(void* const* d_in, const int* in_sizes, int n_in,
                              void* d_out, int out_size)
{
    const float* x  = (const float*)d_in[0];
    const float* Wk = (const float*)d_in[1];
    const float* Wq = (const float*)d_in[2];
    const float* Wv = (const float*)d_in[3];
    const float* Wo = (const float*)d_in[4];
    float* out = (float*)d_out;

    cudaFuncSetAttribute(gemm_mma,
                         cudaFuncAttributeMaxDynamicSharedMemorySize, GEMM_SMEM);
    cudaFuncSetAttribute(attn_mma,
                         cudaFuncAttributeMaxDynamicSharedMemorySize, ATT_SMEM);

    __nv_bfloat16 *xhi, *xlo, *wqh, *wql, *wkh, *wkl, *wvh, *wvl, *woh, *wol;
    __nv_bfloat16 *cxh, *cxl;
    __half *qhi, *qlo, *khi, *vhi, *vlo;
    cudaGetSymbolAddress((void**)&xhi, g_xhi);
    cudaGetSymbolAddress((void**)&xlo, g_xlo);
    cudaGetSymbolAddress((void**)&wqh, g_wq_hi);
    cudaGetSymbolAddress((void**)&wql, g_wq_lo);
    cudaGetSymbolAddress((void**)&wkh, g_wk_hi);
    cudaGetSymbolAddress((void**)&wkl, g_wk_lo);
    cudaGetSymbolAddress((void**)&wvh, g_wv_hi);
    cudaGetSymbolAddress((void**)&wvl, g_wv_lo);
    cudaGetSymbolAddress((void**)&woh, g_wo_hi);
    cudaGetSymbolAddress((void**)&wol, g_wo_lo);
    cudaGetSymbolAddress((void**)&qhi, g_qhi);
    cudaGetSymbolAddress((void**)&qlo, g_qlo);
    cudaGetSymbolAddress((void**)&khi, g_khi);
    cudaGetSymbolAddress((void**)&vhi, g_vhi);
    cudaGetSymbolAddress((void**)&vlo, g_vlo);
    cudaGetSymbolAddress((void**)&cxh, g_cxhi);
    cudaGetSymbolAddress((void**)&cxl, g_cxlo);

    prep_x_kernel<<<1024, 256>>>(x, xhi, xlo, ROWS * DM);
    prep_w_heads_kernel<<<dim3(32, 2, 16), 256>>>(Wq, wqh, wql);
    prep_w_heads_kernel<<<dim3(32, 2, 16), 256>>>(Wk, wkh, wkl);
    prep_w_heads_kernel<<<dim3(32, 2, 16), 256>>>(Wv, wvh, wvl);
    prep_wo_kernel<<<dim3(32, 32), 256>>>(Wo, woh, wol);

    QKVPtrs p;
    p.bh0 = wqh; p.bl0 = wql; p.oh0 = qhi; p.ol0 = qlo;
    p.bh1 = wkh; p.bl1 = wkl; p.oh1 = khi;
    p.bh2 = wvh; p.bl2 = wvl; p.oh2 = vhi; p.ol2 = vlo;

    gemm_mma<<<dim3(32, 8, 3), 256, GEMM_SMEM>>>(xhi, xlo, nullptr, nullptr,
                                                 nullptr, p, 1);

    attn_mma<<<dim3(S_ / 128, BH), 128, ATT_SMEM>>>();

    QKVPtrs dummy = {};
    gemm_mma<<<dim3(32, 8), 256, GEMM_SMEM>>>(cxh, cxl, woh, wol,
                                              out, dummy, 0);
}

// round 8
// speedup vs baseline: 3.9767x; 1.1827x over previous
#include <cuda_runtime.h>
#include <cuda_bf16.h>
#include <cuda_fp16.h>
#include <math_constants.h>
#include <cstdint>

#define B_  2
#define S_  2048
#define DM  1024
#define DK  64
#define H_  16
#define BH  (B_ * H_)
#define ROWS (B_ * S_)          // 4096

// ---------------------------------------------------------------------------
// Scratch (allocation-free: device globals)
// ---------------------------------------------------------------------------
__device__ __nv_bfloat16 g_xhi[ROWS * DM], g_xlo[ROWS * DM];
__device__ __nv_bfloat16 g_wq_hi[DM * DM], g_wq_lo[DM * DM];
__device__ __nv_bfloat16 g_wk_hi[DM * DM], g_wk_lo[DM * DM];
__device__ __nv_bfloat16 g_wv_hi[DM * DM], g_wv_lo[DM * DM];
__device__ __nv_bfloat16 g_wo_hi[DM * DM], g_wo_lo[DM * DM];
__device__ __half g_qhi[BH * S_ * DK];
__device__ __half g_khi[BH * S_ * DK];
__device__ __half g_vhi[BH * S_ * DK], g_vlo[BH * S_ * DK];
__device__ __nv_bfloat16 g_cxhi[ROWS * DM], g_cxlo[ROWS * DM];

// Q pre-scale: (1/sqrt(64)) * log2(e)  -> softmax computed in base-2
#define Q_ALPHA 0.18033688011112042f

// ---------------------------------------------------------------------------
// Helpers
// ---------------------------------------------------------------------------
__device__ __forceinline__ uint32_t smem_to_u32(const void* p) {
    uint32_t a;
    asm("{ .reg .u64 t; cvta.to.shared.u64 t, %1; cvt.u32.u64 %0, t; }"
        : "=r"(a) : "l"(p));
    return a;
}
// bf16 mma
__device__ __forceinline__ void mma16816(float* c, const uint32_t* a, const uint32_t* b) {
    asm volatile("mma.sync.aligned.m16n8k16.row.col.f32.bf16.bf16.f32 "
        "{%0,%1,%2,%3}, {%4,%5,%6,%7}, {%8,%9}, {%0,%1,%2,%3};"
        : "+f"(c[0]), "+f"(c[1]), "+f"(c[2]), "+f"(c[3])
        : "r"(a[0]), "r"(a[1]), "r"(a[2]), "r"(a[3]), "r"(b[0]), "r"(b[1]));
}
// fp16 mma
__device__ __forceinline__ void mma16816h(float* c, const uint32_t* a, const uint32_t* b) {
    asm volatile("mma.sync.aligned.m16n8k16.row.col.f32.f16.f16.f32 "
        "{%0,%1,%2,%3}, {%4,%5,%6,%7}, {%8,%9}, {%0,%1,%2,%3};"
        : "+f"(c[0]), "+f"(c[1]), "+f"(c[2]), "+f"(c[3])
        : "r"(a[0]), "r"(a[1]), "r"(a[2]), "r"(a[3]), "r"(b[0]), "r"(b[1]));
}
__device__ __forceinline__ void ldsm_x4(uint32_t* r, uint32_t a) {
    asm volatile("ldmatrix.sync.aligned.m8n8.x4.shared.b16 {%0,%1,%2,%3}, [%4];"
        : "=r"(r[0]), "=r"(r[1]), "=r"(r[2]), "=r"(r[3]) : "r"(a));
}
__device__ __forceinline__ void ldsm_x4_t(uint32_t* r, uint32_t a) {
    asm volatile("ldmatrix.sync.aligned.m8n8.x4.trans.shared.b16 {%0,%1,%2,%3}, [%4];"
        : "=r"(r[0]), "=r"(r[1]), "=r"(r[2]), "=r"(r[3]) : "r"(a));
}
__device__ __forceinline__ void cp16(uint32_t d, const void* s) {
    asm volatile("cp.async.cg.shared.global [%0], [%1], 16;" :: "r"(d), "l"(s));
}
#define CP_COMMIT asm volatile("cp.async.commit_group;" ::: "memory")
#define CP_WAIT1  asm volatile("cp.async.wait_group 1;" ::: "memory")
#define CP_WAIT0  asm volatile("cp.async.wait_group 0;" ::: "memory")

__device__ __forceinline__ uint32_t packbf(float lo, float hi) {
    uint32_t r;
    asm("cvt.rn.bf16x2.f32 %0, %1, %2;" : "=r"(r) : "f"(hi), "f"(lo));
    return r;
}
__device__ __forceinline__ uint32_t packh(float lo, float hi) {
    uint32_t r;
    asm("cvt.rn.f16x2.f32 %0, %1, %2;" : "=r"(r) : "f"(hi), "f"(lo));
    return r;
}

// ---------------------------------------------------------------------------
// Prep kernels (fp32 -> bf16 hi/lo)
// ---------------------------------------------------------------------------
__global__ void prep_x_kernel(const float* __restrict__ x,
                              __nv_bfloat16* __restrict__ hi,
                              __nv_bfloat16* __restrict__ lo, int n)
{
    for (int i = blockIdx.x * blockDim.x + threadIdx.x; i < n;
         i += gridDim.x * blockDim.x) {
        float v = x[i];
        __nv_bfloat16 h = __float2bfloat16(v);
        hi[i] = h;
        lo[i] = __float2bfloat16(v - __bfloat162float(h));
    }
}

__global__ void prep_w_heads_kernel(const float* __restrict__ W,
                                    __nv_bfloat16* __restrict__ hi,
                                    __nv_bfloat16* __restrict__ lo)
{
    __shared__ float tile[32][33];
    int t = threadIdx.x, tx = t & 31, ty = t >> 5;
    int k0 = blockIdx.x * 32, c0 = blockIdx.y * 32, h = blockIdx.z;
    const float* src = W + (size_t)h * DM * DK;
    #pragma unroll
    for (int i = 0; i < 32; i += 8)
        tile[ty + i][tx] = src[(size_t)(k0 + ty + i) * DK + c0 + tx];
    __syncthreads();
    #pragma unroll
    for (int i = 0; i < 32; i += 8) {
        int n = h * 64 + c0 + ty + i;
        float v = tile[tx][ty + i];
        __nv_bfloat16 hh = __float2bfloat16(v);
        hi[(size_t)n * DM + k0 + tx] = hh;
        lo[(size_t)n * DM + k0 + tx] = __float2bfloat16(v - __bfloat162float(hh));
    }
}

__global__ void prep_wo_kernel(const float* __restrict__ W,
                               __nv_bfloat16* __restrict__ hi,
                               __nv_bfloat16* __restrict__ lo)
{
    __shared__ float tile[32][33];
    int t = threadIdx.x, tx = t & 31, ty = t >> 5;
    int k0 = blockIdx.x * 32, n0 = blockIdx.y * 32;
    #pragma unroll
    for (int i = 0; i < 32; i += 8)
        tile[ty + i][tx] = W[(size_t)(k0 + ty + i) * DM + n0 + tx];
    __syncthreads();
    #pragma unroll
    for (int i = 0; i < 32; i += 8) {
        int n = n0 + ty + i;
        float v = tile[tx][ty + i];
        __nv_bfloat16 hh = __float2bfloat16(v);
        hi[(size_t)n * DM + k0 + tx] = hh;
        lo[(size_t)n * DM + k0 + tx] = __float2bfloat16(v - __bfloat162float(hh));
    }
}

// ---------------------------------------------------------------------------
// HMMA bf16-split GEMM. mode 1 (fused QKV, blockIdx.z selects proj):
//   z=0: Q -> fp16 hi only, scaled by Q_ALPHA
//   z=1: K -> fp16 hi only
//   z=2: V -> fp16 hi/lo
// mode 0: fp32 row-major out (output projection)
// ---------------------------------------------------------------------------
struct QKVPtrs {
    const __nv_bfloat16 *bh0, *bl0, *bh1, *bl1, *bh2, *bl2;
    __half *oh0, *oh1, *oh2, *ol2;
};

#define GBK 32
#define GSTRIDE 40
#define GPLANE (128 * GSTRIDE * 2)      // 10240 B
#define GSTAGE (4 * GPLANE)             // 40960 B
#define GEMM_SMEM (2 * GSTAGE)          // 81920 B

__global__ __launch_bounds__(256) void gemm_mma(
    const __nv_bfloat16* __restrict__ Ahi, const __nv_bfloat16* __restrict__ Alo,
    const __nv_bfloat16* __restrict__ Bhi_p, const __nv_bfloat16* __restrict__ Blo_p,
    float* __restrict__ outf, QKVPtrs p, int mode)
{
    extern __shared__ char smem[];
    const uint32_t sb = smem_to_u32(smem);
    const int t = threadIdx.x, w = t >> 5, ln = t & 31;
    const int wm = (w & 1) * 64, wn = (w >> 1) * 32;
    const int row0 = blockIdx.x * 128, col0 = blockIdx.y * 128;

    const __nv_bfloat16 *Bhi = Bhi_p, *Blo = Blo_p;
    __half *outhi = nullptr, *outlo = nullptr;
    float alpha = 1.0f;
    int z = -1;
    if (mode == 1) {
        z = blockIdx.z;
        if (z == 0) { Bhi = p.bh0; Blo = p.bl0; outhi = p.oh0; alpha = Q_ALPHA; }
        else if (z == 1) { Bhi = p.bh1; Blo = p.bl1; outhi = p.oh1; }
        else { Bhi = p.bh2; Blo = p.bl2; outhi = p.oh2; outlo = p.ol2; }
    }

    const __nv_bfloat16* src[4] = {
        Ahi + (size_t)row0 * DM, Alo + (size_t)row0 * DM,
        Bhi + (size_t)col0 * DM, Blo + (size_t)col0 * DM };

    const int ldr0 = t >> 2, ldseg = t & 3;

    float c[4][4][4] = {};

    {
        #pragma unroll
        for (int pi = 0; pi < 4; pi++)
            #pragma unroll
            for (int j = 0; j < 2; j++) {
                int row = ldr0 + j * 64;
                cp16(sb + pi * GPLANE + row * 80 + ldseg * 16,
                     src[pi] + (size_t)row * DM + ldseg * 8);
            }
        CP_COMMIT;
    }

    for (int kc = 0; kc < DM / GBK; kc++) {
        if (kc + 1 < DM / GBK) {
            int k0 = (kc + 1) * GBK;
            uint32_t stn = sb + ((kc + 1) & 1) * GSTAGE;
            #pragma unroll
            for (int pi = 0; pi < 4; pi++)
                #pragma unroll
                for (int j = 0; j < 2; j++) {
                    int row = ldr0 + j * 64;
                    cp16(stn + pi * GPLANE + row * 80 + ldseg * 16,
                         src[pi] + (size_t)row * DM + k0 + ldseg * 8);
                }
            CP_COMMIT;
            CP_WAIT1;
        } else {
            CP_WAIT0;
        }
        __syncthreads();
        uint32_t st = sb + (kc & 1) * GSTAGE;

        #pragma unroll
        for (int ks = 0; ks < 2; ks++) {
            uint32_t bh[4][2], bl[4][2];
            #pragma unroll
            for (int np = 0; np < 2; np++) {
                uint32_t baddr = st + 2 * GPLANE
                    + (wn + np * 16 + ((ln >> 4) & 1) * 8 + (ln & 7)) * 80
                    + ks * 32 + ((ln >> 3) & 1) * 16;
                uint32_t r[4];
                ldsm_x4(r, baddr);
                bh[2*np][0] = r[0]; bh[2*np][1] = r[1];
                bh[2*np+1][0] = r[2]; bh[2*np+1][1] = r[3];
                ldsm_x4(r, baddr + GPLANE);
                bl[2*np][0] = r[0]; bl[2*np][1] = r[1];
                bl[2*np+1][0] = r[2]; bl[2*np+1][1] = r[3];
            }
            #pragma unroll
            for (int mi = 0; mi < 4; mi++) {
                uint32_t aaddr = st + (wm + mi * 16 + (ln & 15)) * 80
                               + ks * 32 + (ln >> 4) * 16;
                uint32_t ah[4], al[4];
                ldsm_x4(ah, aaddr);
                ldsm_x4(al, aaddr + GPLANE);
                #pragma unroll
                for (int ni = 0; ni < 4; ni++) {
                    mma16816(c[mi][ni], ah, bh[ni]);
                    mma16816(c[mi][ni], ah, bl[ni]);
                    mma16816(c[mi][ni], al, bh[ni]);
                }
            }
        }
        __syncthreads();
    }

    #pragma unroll
    for (int mi = 0; mi < 4; mi++) {
        int r = row0 + wm + mi * 16 + (ln >> 2);
        #pragma unroll
        for (int ni = 0; ni < 4; ni++) {
            int cc = col0 + wn + ni * 8 + 2 * (ln & 3);
            if (mode == 0) {
                *(float2*)&outf[(size_t)r * DM + cc] =
                    make_float2(c[mi][ni][0], c[mi][ni][1]);
                *(float2*)&outf[(size_t)(r + 8) * DM + cc] =
                    make_float2(c[mi][ni][2], c[mi][ni][3]);
            } else {
                int h = cc >> 6, d = cc & 63;
                #pragma unroll
                for (int rr = 0; rr < 2; rr++) {
                    int row = r + rr * 8;
                    int b = row >> 11, s = row & (S_ - 1);
                    size_t idx = ((size_t)((b << 4) + h) * S_ + s) * DK + d;
                    float v0 = c[mi][ni][2 * rr + 0] * alpha;
                    float v1 = c[mi][ni][2 * rr + 1] * alpha;
                    uint32_t ph = packh(v0, v1);
                    *(uint32_t*)&outhi[idx] = ph;
                    if (z == 2) {
                        __half2 h2 = *(__half2*)&ph;
                        float r0 = v0 - __half2float(__low2half(h2));
                        float r1 = v1 - __half2float(__high2half(h2));
                        *(uint32_t*)&outlo[idx] = packh(r0, r1);
                    }
                }
            }
        }
    }
}

// ---------------------------------------------------------------------------
// FP16 flash attention: 4 warps, warp tile m=32 x 64 t, 2 CTAs/SM.
// scores = qh*kh (1 product); PV = ph*Vh + ph*Vl (2 products).
// Softmax in base-2 (Q pre-scaled by log2 e / 8).
// ---------------------------------------------------------------------------
#define AT_STRIDE 72                     // padded elems (144 B)
#define AT_PLANE (64 * AT_STRIDE * 2)    // 9216 B
#define AT_STAGE (3 * AT_PLANE)          // 27648 : Kh, Vh, Vl
#define ATT_SMEM (2 * AT_STAGE)          // 55296

__global__ __launch_bounds__(128, 2) void attn_mma()
{
    extern __shared__ char smem[];
    const uint32_t sb = smem_to_u32(smem);
    const int t = threadIdx.x, w = t >> 5, ln = t & 31;
    const int bh = blockIdx.y, q0 = blockIdx.x * 128;
    const size_t hbase = (size_t)bh * S_ * DK;

    // Q fragments (fp16, pre-scaled by Q_ALPHA)
    uint32_t qh[4][8];
    #pragma unroll
    for (int mi = 0; mi < 2; mi++) {
        int r = q0 + w * 32 + mi * 16 + (ln >> 2);
        int cb = 2 * (ln & 3);
        #pragma unroll
        for (int ks = 0; ks < 4; ks++) {
            int c0 = ks * 16 + cb;
            qh[ks][mi*4+0] = *(const uint32_t*)&g_qhi[hbase + (size_t)r * DK + c0];
            qh[ks][mi*4+1] = *(const uint32_t*)&g_qhi[hbase + (size_t)(r + 8) * DK + c0];
            qh[ks][mi*4+2] = *(const uint32_t*)&g_qhi[hbase + (size_t)r * DK + c0 + 8];
            qh[ks][mi*4+3] = *(const uint32_t*)&g_qhi[hbase + (size_t)(r + 8) * DK + c0 + 8];
        }
    }

    float ctx[2][8][4] = {};
    float mx[2][2], ls[2][2];
    #pragma unroll
    for (int i = 0; i < 2; i++) {
        mx[i][0] = -CUDART_INF_F; mx[i][1] = -CUDART_INF_F;
        ls[i][0] = 0.f; ls[i][1] = 0.f;
    }

    const __half* gsrc[3] = { g_khi + hbase, g_vhi + hbase, g_vlo + hbase };
    const int krow = t >> 3, kseg = t & 7;

    {
        #pragma unroll
        for (int pi = 0; pi < 3; pi++)
            #pragma unroll
            for (int j = 0; j < 4; j++) {
                int row = krow + j * 16;
                cp16(sb + pi * AT_PLANE + row * 144 + kseg * 16,
                     gsrc[pi] + (size_t)row * DK + kseg * 8);
            }
        CP_COMMIT;
    }

    for (int it = 0; it < S_ / 64; it++) {
        if (it + 1 < S_ / 64) {
            uint32_t stn = sb + ((it + 1) & 1) * AT_STAGE;
            #pragma unroll
            for (int pi = 0; pi < 3; pi++)
                #pragma unroll
                for (int j = 0; j < 4; j++) {
                    int row = krow + j * 16;
                    cp16(stn + pi * AT_PLANE + row * 144 + kseg * 16,
                         gsrc[pi] + (size_t)((it + 1) * 64 + row) * DK + kseg * 8);
                }
            CP_COMMIT;
            CP_WAIT1;
        } else {
            CP_WAIT0;
        }
        __syncthreads();
        uint32_t st = sb + (it & 1) * AT_STAGE;

        #pragma unroll
        for (int half = 0; half < 2; half++) {
            // ---- scores: single-product fp16 (qh*kh) ----
            float sc[2][4][4] = {};
            #pragma unroll
            for (int ks = 0; ks < 4; ks++) {
                #pragma unroll
                for (int np = 0; np < 2; np++) {
                    uint32_t baddr = st
                        + (half * 32 + np * 16 + ((ln >> 4) & 1) * 8 + (ln & 7)) * 144
                        + ks * 32 + ((ln >> 3) & 1) * 16;
                    uint32_t rh[4];
                    ldsm_x4(rh, baddr);
                    uint32_t b0[2] = { rh[0], rh[1] }, b1[2] = { rh[2], rh[3] };
                    #pragma unroll
                    for (int mi = 0; mi < 2; mi++) {
                        mma16816h(sc[mi][2*np],   qh[ks] + mi*4, b0);
                        mma16816h(sc[mi][2*np+1], qh[ks] + mi*4, b1);
                    }
                }
            }

            // ---- online softmax (base-2) ----
            #pragma unroll
            for (int mi = 0; mi < 2; mi++) {
                float rm0 = -CUDART_INF_F, rm1 = -CUDART_INF_F;
                #pragma unroll
                for (int nj = 0; nj < 4; nj++) {
                    rm0 = fmaxf(rm0, fmaxf(sc[mi][nj][0], sc[mi][nj][1]));
                    rm1 = fmaxf(rm1, fmaxf(sc[mi][nj][2], sc[mi][nj][3]));
                }
                rm0 = fmaxf(rm0, __shfl_xor_sync(0xffffffffu, rm0, 1));
                rm0 = fmaxf(rm0, __shfl_xor_sync(0xffffffffu, rm0, 2));
                rm1 = fmaxf(rm1, __shfl_xor_sync(0xffffffffu, rm1, 1));
                rm1 = fmaxf(rm1, __shfl_xor_sync(0xffffffffu, rm1, 2));
                float mn0 = fmaxf(mx[mi][0], rm0), mn1 = fmaxf(mx[mi][1], rm1);
                float a0 = exp2f(mx[mi][0] - mn0), a1 = exp2f(mx[mi][1] - mn1);
                mx[mi][0] = mn0; mx[mi][1] = mn1;
                float rs0 = 0.f, rs1 = 0.f;
                #pragma unroll
                for (int nj = 0; nj < 4; nj++) {
                    sc[mi][nj][0] = exp2f(sc[mi][nj][0] - mn0);
                    sc[mi][nj][1] = exp2f(sc[mi][nj][1] - mn0);
                    sc[mi][nj][2] = exp2f(sc[mi][nj][2] - mn1);
                    sc[mi][nj][3] = exp2f(sc[mi][nj][3] - mn1);
                    rs0 += sc[mi][nj][0] + sc[mi][nj][1];
                    rs1 += sc[mi][nj][2] + sc[mi][nj][3];
                }
                rs0 += __shfl_xor_sync(0xffffffffu, rs0, 1);
                rs0 += __shfl_xor_sync(0xffffffffu, rs0, 2);
                rs1 += __shfl_xor_sync(0xffffffffu, rs1, 1);
                rs1 += __shfl_xor_sync(0xffffffffu, rs1, 2);
                ls[mi][0] = ls[mi][0] * a0 + rs0;
                ls[mi][1] = ls[mi][1] * a1 + rs1;
                #pragma unroll
                for (int vt = 0; vt < 8; vt++) {
                    ctx[mi][vt][0] *= a0; ctx[mi][vt][1] *= a0;
                    ctx[mi][vt][2] *= a1; ctx[mi][vt][3] *= a1;
                }
            }

            // ---- P fragments (fp16) by register reinterleave ----
            uint32_t ph[2][2][4];
            #pragma unroll
            for (int mi = 0; mi < 2; mi++)
                #pragma unroll
                for (int kk = 0; kk < 2; kk++)
                    #pragma unroll
                    for (int e = 0; e < 4; e++) {
                        int tile = 2 * kk + (e >> 1);
                        int o = (e & 1) * 2;
                        ph[mi][kk][e] = packh(sc[mi][tile][o], sc[mi][tile][o + 1]);
                    }

            // ---- ctx += P * (Vh + Vl) (2 products) ----
            #pragma unroll
            for (int kk = 0; kk < 2; kk++) {
                #pragma unroll
                for (int vp = 0; vp < 4; vp++) {
                    uint32_t vaddr = st + 1 * AT_PLANE
                        + (half * 32 + kk * 16 + ((ln >> 3) & 1) * 8 + (ln & 7)) * 144
                        + vp * 32 + ((ln >> 4) & 1) * 16;
                    uint32_t rh[4], rl[4];
                    ldsm_x4_t(rh, vaddr);
                    ldsm_x4_t(rl, vaddr + AT_PLANE);
                    uint32_t b0[2] = { rh[0], rh[1] }, b1[2] = { rh[2], rh[3] };
                    uint32_t l0[2] = { rl[0], rl[1] }, l1[2] = { rl[2], rl[3] };
                    #pragma unroll
                    for (int mi = 0; mi < 2; mi++) {
                        mma16816h(ctx[mi][2*vp],   ph[mi][kk], b0);
                        mma16816h(ctx[mi][2*vp],   ph[mi][kk], l0);
                        mma16816h(ctx[mi][2*vp+1], ph[mi][kk], b1);
                        mma16816h(ctx[mi][2*vp+1], ph[mi][kk], l1);
                    }
                }
            }
        }
        __syncthreads();
    }

    // ---- epilogue: ctx -> bf16 hi/lo (bit-trick residuals) ----
    const int b = bh >> 4, h = bh & 15;
    #pragma unroll
    for (int mi = 0; mi < 2; mi++) {
        float inv0 = 1.f / ls[mi][0], inv1 = 1.f / ls[mi][1];
        int r = q0 + w * 32 + mi * 16 + (ln >> 2);
        size_t ob0 = ((size_t)(b * S_ + r)) * DM + h * 64;
        size_t ob1 = ob0 + (size_t)8 * DM;
        #pragma unroll
        for (int vt = 0; vt < 8; vt++) {
            int cc = vt * 8 + 2 * (ln & 3);
            float v0 = ctx[mi][vt][0] * inv0, v1 = ctx[mi][vt][1] * inv0;
            float v2 = ctx[mi][vt][2] * inv1, v3 = ctx[mi][vt][3] * inv1;
            uint32_t pA = packbf(v0, v1);
            uint32_t pB = packbf(v2, v3);
            *(uint32_t*)&g_cxhi[ob0 + cc] = pA;
            *(uint32_t*)&g_cxhi[ob1 + cc] = pB;
            *(uint32_t*)&g_cxlo[ob0 + cc] =
                packbf(v0 - __uint_as_float(pA << 16),
                       v1 - __uint_as_float(pA & 0xFFFF0000u));
            *(uint32_t*)&g_cxlo[ob1 + cc] =
                packbf(v2 - __uint_as_float(pB << 16),
                       v3 - __uint_as_float(pB & 0xFFFF0000u));
        }
    }
}

// ---------------------------------------------------------------------------
// Launch. Input order per metadata: x, Wk, Wq, Wv, Wo
// ---------------------------------------------------------------------------
extern "C" void kernel_launch(void* const* d_in, const int* in_sizes, int n_in,
                              void* d_out, int out_size)
{
    const float* x  = (const float*)d_in[0];
    const float* Wk = (const float*)d_in[1];
    const float* Wq = (const float*)d_in[2];
    const float* Wv = (const float*)d_in[3];
    const float* Wo = (const float*)d_in[4];
    float* out = (float*)d_out;

    cudaFuncSetAttribute(gemm_mma,
                         cudaFuncAttributeMaxDynamicSharedMemorySize, GEMM_SMEM);
    cudaFuncSetAttribute(attn_mma,
                         cudaFuncAttributeMaxDynamicSharedMemorySize, ATT_SMEM);

    __nv_bfloat16 *xhi, *xlo, *wqh, *wql, *wkh, *wkl, *wvh, *wvl, *woh, *wol;
    __nv_bfloat16 *cxh, *cxl;
    __half *qhi, *khi, *vhi, *vlo;
    cudaGetSymbolAddress((void**)&xhi, g_xhi);
    cudaGetSymbolAddress((void**)&xlo, g_xlo);
    cudaGetSymbolAddress((void**)&wqh, g_wq_hi);
    cudaGetSymbolAddress((void**)&wql, g_wq_lo);
    cudaGetSymbolAddress((void**)&wkh, g_wk_hi);
    cudaGetSymbolAddress((void**)&wkl, g_wk_lo);
    cudaGetSymbolAddress((void**)&wvh, g_wv_hi);
    cudaGetSymbolAddress((void**)&wvl, g_wv_lo);
    cudaGetSymbolAddress((void**)&woh, g_wo_hi);
    cudaGetSymbolAddress((void**)&wol, g_wo_lo);
    cudaGetSymbolAddress((void**)&qhi, g_qhi);
    cudaGetSymbolAddress((void**)&khi, g_khi);
    cudaGetSymbolAddress((void**)&vhi, g_vhi);
    cudaGetSymbolAddress((void**)&vlo, g_vlo);
    cudaGetSymbolAddress((void**)&cxh, g_cxhi);
    cudaGetSymbolAddress((void**)&cxl, g_cxlo);

    prep_x_kernel<<<1024, 256>>>(x, xhi, xlo, ROWS * DM);
    prep_w_heads_kernel<<<dim3(32, 2, 16), 256>>>(Wq, wqh, wql);
    prep_w_heads_kernel<<<dim3(32, 2, 16), 256>>>(Wk, wkh, wkl);
    prep_w_heads_kernel<<<dim3(32, 2, 16), 256>>>(Wv, wvh, wvl);
    prep_wo_kernel<<<dim3(32, 32), 256>>>(Wo, woh, wol);

    QKVPtrs p;
    p.bh0 = wqh; p.bl0 = wql; p.oh0 = qhi;
    p.bh1 = wkh; p.bl1 = wkl; p.oh1 = khi;
    p.bh2 = wvh; p.bl2 = wvl; p.oh2 = vhi; p.ol2 = vlo;

    gemm_mma<<<dim3(32, 8, 3), 256, GEMM_SMEM>>>(xhi, xlo, nullptr, nullptr,
                                                 nullptr, p, 1);

    attn_mma<<<dim3(S_ / 128, BH), 128, ATT_SMEM>>>();

    QKVPtrs dummy = {};
    gemm_mma<<<dim3(32, 8), 256, GEMM_SMEM>>>(cxh, cxl, woh, wol,
                                              out, dummy, 0);
}

// round 9
// speedup vs baseline: 5.0830x; 1.2782x over previous
#include <cuda_runtime.h>
#include <cuda_bf16.h>
#include <cuda_fp16.h>
#include <math_constants.h>
#include <cstdint>

#define B_  2
#define S_  2048
#define DM  1024
#define DK  64
#define H_  16
#define BH  (B_ * H_)
#define ROWS (B_ * S_)          // 4096

// ---------------------------------------------------------------------------
// Scratch (allocation-free: device globals)
// ---------------------------------------------------------------------------
__device__ __half g_xh[ROWS * DM], g_xl[ROWS * DM];
__device__ __half g_wq[DM * DM], g_wk[DM * DM], g_wv[DM * DM];
__device__ __nv_bfloat16 g_wo_hi[DM * DM], g_wo_lo[DM * DM];
__device__ __half g_q[BH * S_ * DK], g_k[BH * S_ * DK], g_v[BH * S_ * DK];
__device__ __nv_bfloat16 g_cxhi[ROWS * DM], g_cxlo[ROWS * DM];

// Q pre-scale: (1/sqrt(64)) * log2(e)  -> softmax computed in base-2
#define Q_ALPHA 0.18033688011112042f

// ---------------------------------------------------------------------------
// Helpers
// ---------------------------------------------------------------------------
__device__ __forceinline__ uint32_t smem_to_u32(const void* p) {
    uint32_t a;
    asm("{ .reg .u64 t; cvta.to.shared.u64 t, %1; cvt.u32.u64 %0, t; }"
        : "=r"(a) : "l"(p));
    return a;
}
// bf16 mma
__device__ __forceinline__ void mma16816(float* c, const uint32_t* a, const uint32_t* b) {
    asm volatile("mma.sync.aligned.m16n8k16.row.col.f32.bf16.bf16.f32 "
        "{%0,%1,%2,%3}, {%4,%5,%6,%7}, {%8,%9}, {%0,%1,%2,%3};"
        : "+f"(c[0]), "+f"(c[1]), "+f"(c[2]), "+f"(c[3])
        : "r"(a[0]), "r"(a[1]), "r"(a[2]), "r"(a[3]), "r"(b[0]), "r"(b[1]));
}
// fp16 mma
__device__ __forceinline__ void mma16816h(float* c, const uint32_t* a, const uint32_t* b) {
    asm volatile("mma.sync.aligned.m16n8k16.row.col.f32.f16.f16.f32 "
        "{%0,%1,%2,%3}, {%4,%5,%6,%7}, {%8,%9}, {%0,%1,%2,%3};"
        : "+f"(c[0]), "+f"(c[1]), "+f"(c[2]), "+f"(c[3])
        : "r"(a[0]), "r"(a[1]), "r"(a[2]), "r"(a[3]), "r"(b[0]), "r"(b[1]));
}
__device__ __forceinline__ void ldsm_x4(uint32_t* r, uint32_t a) {
    asm volatile("ldmatrix.sync.aligned.m8n8.x4.shared.b16 {%0,%1,%2,%3}, [%4];"
        : "=r"(r[0]), "=r"(r[1]), "=r"(r[2]), "=r"(r[3]) : "r"(a));
}
__device__ __forceinline__ void ldsm_x4_t(uint32_t* r, uint32_t a) {
    asm volatile("ldmatrix.sync.aligned.m8n8.x4.trans.shared.b16 {%0,%1,%2,%3}, [%4];"
        : "=r"(r[0]), "=r"(r[1]), "=r"(r[2]), "=r"(r[3]) : "r"(a));
}
__device__ __forceinline__ void cp16(uint32_t d, const void* s) {
    asm volatile("cp.async.cg.shared.global [%0], [%1], 16;" :: "r"(d), "l"(s));
}
#define CP_COMMIT asm volatile("cp.async.commit_group;" ::: "memory")
#define CP_WAIT1  asm volatile("cp.async.wait_group 1;" ::: "memory")
#define CP_WAIT0  asm volatile("cp.async.wait_group 0;" ::: "memory")

__device__ __forceinline__ uint32_t packbf(float lo, float hi) {
    uint32_t r;
    asm("cvt.rn.bf16x2.f32 %0, %1, %2;" : "=r"(r) : "f"(hi), "f"(lo));
    return r;
}
__device__ __forceinline__ uint32_t packh(float lo, float hi) {
    uint32_t r;
    asm("cvt.rn.f16x2.f32 %0, %1, %2;" : "=r"(r) : "f"(hi), "f"(lo));
    return r;
}

// ---------------------------------------------------------------------------
// Prep kernels
// ---------------------------------------------------------------------------
// x -> fp16 hi/lo split (combined exact to ~2^-22)
__global__ void prep_x_kernel(const float* __restrict__ x,
                              __half* __restrict__ hi,
                              __half* __restrict__ lo, int n)
{
    for (int i = blockIdx.x * blockDim.x + threadIdx.x; i < n;
         i += gridDim.x * blockDim.x) {
        float v = x[i];
        __half h = __float2half_rn(v);
        hi[i] = h;
        lo[i] = __float2half_rn(v - __half2float(h));
    }
}

// W[h][k][c] (16x1024x64) -> dst[n=h*64+c][k] single fp16 plane. grid (32,2,16)
__global__ void prep_w_heads_kernel(const float* __restrict__ W,
                                    __half* __restrict__ dst)
{
    __shared__ float tile[32][33];
    int t = threadIdx.x, tx = t & 31, ty = t >> 5;
    int k0 = blockIdx.x * 32, c0 = blockIdx.y * 32, h = blockIdx.z;
    const float* src = W + (size_t)h * DM * DK;
    #pragma unroll
    for (int i = 0; i < 32; i += 8)
        tile[ty + i][tx] = src[(size_t)(k0 + ty + i) * DK + c0 + tx];
    __syncthreads();
    #pragma unroll
    for (int i = 0; i < 32; i += 8) {
        int n = h * 64 + c0 + ty + i;
        dst[(size_t)n * DM + k0 + tx] = __float2half_rn(tile[tx][ty + i]);
    }
}

// Wo[k][n] -> dst[n][k] bf16 hi/lo. grid (32,32)
__global__ void prep_wo_kernel(const float* __restrict__ W,
                               __nv_bfloat16* __restrict__ hi,
                               __nv_bfloat16* __restrict__ lo)
{
    __shared__ float tile[32][33];
    int t = threadIdx.x, tx = t & 31, ty = t >> 5;
    int k0 = blockIdx.x * 32, n0 = blockIdx.y * 32;
    #pragma unroll
    for (int i = 0; i < 32; i += 8)
        tile[ty + i][tx] = W[(size_t)(k0 + ty + i) * DM + n0 + tx];
    __syncthreads();
    #pragma unroll
    for (int i = 0; i < 32; i += 8) {
        int n = n0 + ty + i;
        float v = tile[tx][ty + i];
        __nv_bfloat16 hh = __float2bfloat16(v);
        hi[(size_t)n * DM + k0 + tx] = hh;
        lo[(size_t)n * DM + k0 + tx] = __float2bfloat16(v - __bfloat162float(hh));
    }
}

// ---------------------------------------------------------------------------
// Common GEMM geometry
// ---------------------------------------------------------------------------
#define GBK 32
#define GSTRIDE 40
#define GPLANE (128 * GSTRIDE * 2)      // 10240 B

// ---------------------------------------------------------------------------
// QKV projection GEMM: fp16 2-product (xh*W + xl*W), fused Q/K/V via z.
// C[4096x1024] = x[4096x1024] * W^T (W stored [n][k]). Out: fp16 per-head.
// ---------------------------------------------------------------------------
#define QSTAGE (3 * GPLANE)             // 30720 : xh, xl, W
#define QKV_SMEM (2 * QSTAGE)           // 61440

__global__ __launch_bounds__(256) void gemm_qkv(
    const __half* __restrict__ xh, const __half* __restrict__ xl)
{
    extern __shared__ char smem[];
    const uint32_t sb = smem_to_u32(smem);
    const int t = threadIdx.x, w = t >> 5, ln = t & 31;
    const int wm = (w & 1) * 64, wn = (w >> 1) * 32;
    const int row0 = blockIdx.x * 128, col0 = blockIdx.y * 128;
    const int z = blockIdx.z;

    const __half* W = (z == 0) ? g_wq : (z == 1) ? g_wk : g_wv;
    __half* out     = (z == 0) ? g_q  : (z == 1) ? g_k  : g_v;
    const float alpha = (z == 0) ? Q_ALPHA : 1.0f;

    const __half* src[3] = {
        xh + (size_t)row0 * DM, xl + (size_t)row0 * DM,
        W + (size_t)col0 * DM };

    const int ldr0 = t >> 2, ldseg = t & 3;

    float c[4][4][4] = {};

    {
        #pragma unroll
        for (int pi = 0; pi < 3; pi++)
            #pragma unroll
            for (int j = 0; j < 2; j++) {
                int row = ldr0 + j * 64;
                cp16(sb + pi * GPLANE + row * 80 + ldseg * 16,
                     src[pi] + (size_t)row * DM + ldseg * 8);
            }
        CP_COMMIT;
    }

    for (int kc = 0; kc < DM / GBK; kc++) {
        if (kc + 1 < DM / GBK) {
            int k0 = (kc + 1) * GBK;
            uint32_t stn = sb + ((kc + 1) & 1) * QSTAGE;
            #pragma unroll
            for (int pi = 0; pi < 3; pi++)
                #pragma unroll
                for (int j = 0; j < 2; j++) {
                    int row = ldr0 + j * 64;
                    cp16(stn + pi * GPLANE + row * 80 + ldseg * 16,
                         src[pi] + (size_t)row * DM + k0 + ldseg * 8);
                }
            CP_COMMIT;
            CP_WAIT1;
        } else {
            CP_WAIT0;
        }
        __syncthreads();
        uint32_t st = sb + (kc & 1) * QSTAGE;

        #pragma unroll
        for (int ks = 0; ks < 2; ks++) {
            uint32_t bh[4][2];
            #pragma unroll
            for (int np = 0; np < 2; np++) {
                uint32_t baddr = st + 2 * GPLANE
                    + (wn + np * 16 + ((ln >> 4) & 1) * 8 + (ln & 7)) * 80
                    + ks * 32 + ((ln >> 3) & 1) * 16;
                uint32_t r[4];
                ldsm_x4(r, baddr);
                bh[2*np][0] = r[0]; bh[2*np][1] = r[1];
                bh[2*np+1][0] = r[2]; bh[2*np+1][1] = r[3];
            }
            #pragma unroll
            for (int mi = 0; mi < 4; mi++) {
                uint32_t aaddr = st + (wm + mi * 16 + (ln & 15)) * 80
                               + ks * 32 + (ln >> 4) * 16;
                uint32_t ah[4], al[4];
                ldsm_x4(ah, aaddr);
                ldsm_x4(al, aaddr + GPLANE);
                #pragma unroll
                for (int ni = 0; ni < 4; ni++) {
                    mma16816h(c[mi][ni], ah, bh[ni]);
                    mma16816h(c[mi][ni], al, bh[ni]);
                }
            }
        }
        __syncthreads();
    }

    // epilogue: fp16 single plane, per-head scatter
    #pragma unroll
    for (int mi = 0; mi < 4; mi++) {
        int r = row0 + wm + mi * 16 + (ln >> 2);
        #pragma unroll
        for (int ni = 0; ni < 4; ni++) {
            int cc = col0 + wn + ni * 8 + 2 * (ln & 3);
            int h = cc >> 6, d = cc & 63;
            #pragma unroll
            for (int rr = 0; rr < 2; rr++) {
                int row = r + rr * 8;
                int b = row >> 11, s = row & (S_ - 1);
                size_t idx = ((size_t)((b << 4) + h) * S_ + s) * DK + d;
                *(uint32_t*)&out[idx] = packh(c[mi][ni][2*rr] * alpha,
                                              c[mi][ni][2*rr+1] * alpha);
            }
        }
    }
}

// ---------------------------------------------------------------------------
// Output projection GEMM: bf16 3-product, fp32 out.
// ---------------------------------------------------------------------------
#define OSTAGE (4 * GPLANE)             // 40960
#define OUT_SMEM (2 * OSTAGE)           // 81920

__global__ __launch_bounds__(256) void gemm_out(float* __restrict__ outf)
{
    extern __shared__ char smem[];
    const uint32_t sb = smem_to_u32(smem);
    const int t = threadIdx.x, w = t >> 5, ln = t & 31;
    const int wm = (w & 1) * 64, wn = (w >> 1) * 32;
    const int row0 = blockIdx.x * 128, col0 = blockIdx.y * 128;

    const __nv_bfloat16* src[4] = {
        g_cxhi + (size_t)row0 * DM, g_cxlo + (size_t)row0 * DM,
        g_wo_hi + (size_t)col0 * DM, g_wo_lo + (size_t)col0 * DM };

    const int ldr0 = t >> 2, ldseg = t & 3;

    float c[4][4][4] = {};

    {
        #pragma unroll
        for (int pi = 0; pi < 4; pi++)
            #pragma unroll
            for (int j = 0; j < 2; j++) {
                int row = ldr0 + j * 64;
                cp16(sb + pi * GPLANE + row * 80 + ldseg * 16,
                     src[pi] + (size_t)row * DM + ldseg * 8);
            }
        CP_COMMIT;
    }

    for (int kc = 0; kc < DM / GBK; kc++) {
        if (kc + 1 < DM / GBK) {
            int k0 = (kc + 1) * GBK;
            uint32_t stn = sb + ((kc + 1) & 1) * OSTAGE;
            #pragma unroll
            for (int pi = 0; pi < 4; pi++)
                #pragma unroll
                for (int j = 0; j < 2; j++) {
                    int row = ldr0 + j * 64;
                    cp16(stn + pi * GPLANE + row * 80 + ldseg * 16,
                         src[pi] + (size_t)row * DM + k0 + ldseg * 8);
                }
            CP_COMMIT;
            CP_WAIT1;
        } else {
            CP_WAIT0;
        }
        __syncthreads();
        uint32_t st = sb + (kc & 1) * OSTAGE;

        #pragma unroll
        for (int ks = 0; ks < 2; ks++) {
            uint32_t bh[4][2], bl[4][2];
            #pragma unroll
            for (int np = 0; np < 2; np++) {
                uint32_t baddr = st + 2 * GPLANE
                    + (wn + np * 16 + ((ln >> 4) & 1) * 8 + (ln & 7)) * 80
                    + ks * 32 + ((ln >> 3) & 1) * 16;
                uint32_t r[4];
                ldsm_x4(r, baddr);
                bh[2*np][0] = r[0]; bh[2*np][1] = r[1];
                bh[2*np+1][0] = r[2]; bh[2*np+1][1] = r[3];
                ldsm_x4(r, baddr + GPLANE);
                bl[2*np][0] = r[0]; bl[2*np][1] = r[1];
                bl[2*np+1][0] = r[2]; bl[2*np+1][1] = r[3];
            }
            #pragma unroll
            for (int mi = 0; mi < 4; mi++) {
                uint32_t aaddr = st + (wm + mi * 16 + (ln & 15)) * 80
                               + ks * 32 + (ln >> 4) * 16;
                uint32_t ah[4], al[4];
                ldsm_x4(ah, aaddr);
                ldsm_x4(al, aaddr + GPLANE);
                #pragma unroll
                for (int ni = 0; ni < 4; ni++) {
                    mma16816(c[mi][ni], ah, bh[ni]);
                    mma16816(c[mi][ni], ah, bl[ni]);
                    mma16816(c[mi][ni], al, bh[ni]);
                }
            }
        }
        __syncthreads();
    }

    #pragma unroll
    for (int mi = 0; mi < 4; mi++) {
        int r = row0 + wm + mi * 16 + (ln >> 2);
        #pragma unroll
        for (int ni = 0; ni < 4; ni++) {
            int cc = col0 + wn + ni * 8 + 2 * (ln & 3);
            *(float2*)&outf[(size_t)r * DM + cc] =
                make_float2(c[mi][ni][0], c[mi][ni][1]);
            *(float2*)&outf[(size_t)(r + 8) * DM + cc] =
                make_float2(c[mi][ni][2], c[mi][ni][3]);
        }
    }
}

// ---------------------------------------------------------------------------
// FP16 flash attention: 4 warps, warp tile m=32 x 64 t, 2 CTAs/SM.
// scores = q*k (1 product); PV = p*v (1 product). Softmax base-2.
// ---------------------------------------------------------------------------
#define AT_STRIDE 72                     // padded elems (144 B)
#define AT_PLANE (64 * AT_STRIDE * 2)    // 9216 B
#define AT_STAGE (2 * AT_PLANE)          // 18432 : Kh, Vh
#define ATT_SMEM (2 * AT_STAGE)          // 36864

__global__ __launch_bounds__(128, 2) void attn_mma()
{
    extern __shared__ char smem[];
    const uint32_t sb = smem_to_u32(smem);
    const int t = threadIdx.x, w = t >> 5, ln = t & 31;
    const int bh = blockIdx.y, q0 = blockIdx.x * 128;
    const size_t hbase = (size_t)bh * S_ * DK;

    // Q fragments (fp16, pre-scaled by Q_ALPHA)
    uint32_t qh[4][8];
    #pragma unroll
    for (int mi = 0; mi < 2; mi++) {
        int r = q0 + w * 32 + mi * 16 + (ln >> 2);
        int cb = 2 * (ln & 3);
        #pragma unroll
        for (int ks = 0; ks < 4; ks++) {
            int c0 = ks * 16 + cb;
            qh[ks][mi*4+0] = *(const uint32_t*)&g_q[hbase + (size_t)r * DK + c0];
            qh[ks][mi*4+1] = *(const uint32_t*)&g_q[hbase + (size_t)(r + 8) * DK + c0];
            qh[ks][mi*4+2] = *(const uint32_t*)&g_q[hbase + (size_t)r * DK + c0 + 8];
            qh[ks][mi*4+3] = *(const uint32_t*)&g_q[hbase + (size_t)(r + 8) * DK + c0 + 8];
        }
    }

    float ctx[2][8][4] = {};
    float mx[2][2], ls[2][2];
    #pragma unroll
    for (int i = 0; i < 2; i++) {
        mx[i][0] = -CUDART_INF_F; mx[i][1] = -CUDART_INF_F;
        ls[i][0] = 0.f; ls[i][1] = 0.f;
    }

    const __half* gsrc[2] = { g_k + hbase, g_v + hbase };
    const int krow = t >> 3, kseg = t & 7;

    {
        #pragma unroll
        for (int pi = 0; pi < 2; pi++)
            #pragma unroll
            for (int j = 0; j < 4; j++) {
                int row = krow + j * 16;
                cp16(sb + pi * AT_PLANE + row * 144 + kseg * 16,
                     gsrc[pi] + (size_t)row * DK + kseg * 8);
            }
        CP_COMMIT;
    }

    for (int it = 0; it < S_ / 64; it++) {
        if (it + 1 < S_ / 64) {
            uint32_t stn = sb + ((it + 1) & 1) * AT_STAGE;
            #pragma unroll
            for (int pi = 0; pi < 2; pi++)
                #pragma unroll
                for (int j = 0; j < 4; j++) {
                    int row = krow + j * 16;
                    cp16(stn + pi * AT_PLANE + row * 144 + kseg * 16,
                         gsrc[pi] + (size_t)((it + 1) * 64 + row) * DK + kseg * 8);
                }
            CP_COMMIT;
            CP_WAIT1;
        } else {
            CP_WAIT0;
        }
        __syncthreads();
        uint32_t st = sb + (it & 1) * AT_STAGE;

        #pragma unroll
        for (int half = 0; half < 2; half++) {
            // ---- scores: single-product fp16 ----
            float sc[2][4][4] = {};
            #pragma unroll
            for (int ks = 0; ks < 4; ks++) {
                #pragma unroll
                for (int np = 0; np < 2; np++) {
                    uint32_t baddr = st
                        + (half * 32 + np * 16 + ((ln >> 4) & 1) * 8 + (ln & 7)) * 144
                        + ks * 32 + ((ln >> 3) & 1) * 16;
                    uint32_t rh[4];
                    ldsm_x4(rh, baddr);
                    uint32_t b0[2] = { rh[0], rh[1] }, b1[2] = { rh[2], rh[3] };
                    #pragma unroll
                    for (int mi = 0; mi < 2; mi++) {
                        mma16816h(sc[mi][2*np],   qh[ks] + mi*4, b0);
                        mma16816h(sc[mi][2*np+1], qh[ks] + mi*4, b1);
                    }
                }
            }

            // ---- online softmax (base-2) ----
            #pragma unroll
            for (int mi = 0; mi < 2; mi++) {
                float rm0 = -CUDART_INF_F, rm1 = -CUDART_INF_F;
                #pragma unroll
                for (int nj = 0; nj < 4; nj++) {
                    rm0 = fmaxf(rm0, fmaxf(sc[mi][nj][0], sc[mi][nj][1]));
                    rm1 = fmaxf(rm1, fmaxf(sc[mi][nj][2], sc[mi][nj][3]));
                }
                rm0 = fmaxf(rm0, __shfl_xor_sync(0xffffffffu, rm0, 1));
                rm0 = fmaxf(rm0, __shfl_xor_sync(0xffffffffu, rm0, 2));
                rm1 = fmaxf(rm1, __shfl_xor_sync(0xffffffffu, rm1, 1));
                rm1 = fmaxf(rm1, __shfl_xor_sync(0xffffffffu, rm1, 2));
                float mn0 = fmaxf(mx[mi][0], rm0), mn1 = fmaxf(mx[mi][1], rm1);
                float a0 = exp2f(mx[mi][0] - mn0), a1 = exp2f(mx[mi][1] - mn1);
                mx[mi][0] = mn0; mx[mi][1] = mn1;
                float rs0 = 0.f, rs1 = 0.f;
                #pragma unroll
                for (int nj = 0; nj < 4; nj++) {
                    sc[mi][nj][0] = exp2f(sc[mi][nj][0] - mn0);
                    sc[mi][nj][1] = exp2f(sc[mi][nj][1] - mn0);
                    sc[mi][nj][2] = exp2f(sc[mi][nj][2] - mn1);
                    sc[mi][nj][3] = exp2f(sc[mi][nj][3] - mn1);
                    rs0 += sc[mi][nj][0] + sc[mi][nj][1];
                    rs1 += sc[mi][nj][2] + sc[mi][nj][3];
                }
                rs0 += __shfl_xor_sync(0xffffffffu, rs0, 1);
                rs0 += __shfl_xor_sync(0xffffffffu, rs0, 2);
                rs1 += __shfl_xor_sync(0xffffffffu, rs1, 1);
                rs1 += __shfl_xor_sync(0xffffffffu, rs1, 2);
                ls[mi][0] = ls[mi][0] * a0 + rs0;
                ls[mi][1] = ls[mi][1] * a1 + rs1;
                #pragma unroll
                for (int vt = 0; vt < 8; vt++) {
                    ctx[mi][vt][0] *= a0; ctx[mi][vt][1] *= a0;
                    ctx[mi][vt][2] *= a1; ctx[mi][vt][3] *= a1;
                }
            }

            // ---- P fragments (fp16) by register reinterleave ----
            uint32_t ph[2][2][4];
            #pragma unroll
            for (int mi = 0; mi < 2; mi++)
                #pragma unroll
                for (int kk = 0; kk < 2; kk++)
                    #pragma unroll
                    for (int e = 0; e < 4; e++) {
                        int tile = 2 * kk + (e >> 1);
                        int o = (e & 1) * 2;
                        ph[mi][kk][e] = packh(sc[mi][tile][o], sc[mi][tile][o + 1]);
                    }

            // ---- ctx += P * V (1 product) ----
            #pragma unroll
            for (int kk = 0; kk < 2; kk++) {
                #pragma unroll
                for (int vp = 0; vp < 4; vp++) {
                    uint32_t vaddr = st + AT_PLANE
                        + (half * 32 + kk * 16 + ((ln >> 3) & 1) * 8 + (ln & 7)) * 144
                        + vp * 32 + ((ln >> 4) & 1) * 16;
                    uint32_t rh[4];
                    ldsm_x4_t(rh, vaddr);
                    uint32_t b0[2] = { rh[0], rh[1] }, b1[2] = { rh[2], rh[3] };
                    #pragma unroll
                    for (int mi = 0; mi < 2; mi++) {
                        mma16816h(ctx[mi][2*vp],   ph[mi][kk], b0);
                        mma16816h(ctx[mi][2*vp+1], ph[mi][kk], b1);
                    }
                }
            }
        }
        __syncthreads();
    }

    // ---- epilogue: ctx -> bf16 hi/lo (bit-trick residuals) ----
    const int b = bh >> 4, h = bh & 15;
    #pragma unroll
    for (int mi = 0; mi < 2; mi++) {
        float inv0 = 1.f / ls[mi][0], inv1 = 1.f / ls[mi][1];
        int r = q0 + w * 32 + mi * 16 + (ln >> 2);
        size_t ob0 = ((size_t)(b * S_ + r)) * DM + h * 64;
        size_t ob1 = ob0 + (size_t)8 * DM;
        #pragma unroll
        for (int vt = 0; vt < 8; vt++) {
            int cc = vt * 8 + 2 * (ln & 3);
            float v0 = ctx[mi][vt][0] * inv0, v1 = ctx[mi][vt][1] * inv0;
            float v2 = ctx[mi][vt][2] * inv1, v3 = ctx[mi][vt][3] * inv1;
            uint32_t pA = packbf(v0, v1);
            uint32_t pB = packbf(v2, v3);
            *(uint32_t*)&g_cxhi[ob0 + cc] = pA;
            *(uint32_t*)&g_cxhi[ob1 + cc] = pB;
            *(uint32_t*)&g_cxlo[ob0 + cc] =
                packbf(v0 - __uint_as_float(pA << 16),
                       v1 - __uint_as_float(pA & 0xFFFF0000u));
            *(uint32_t*)&g_cxlo[ob1 + cc] =
                packbf(v2 - __uint_as_float(pB << 16),
                       v3 - __uint_as_float(pB & 0xFFFF0000u));
        }
    }
}

// ---------------------------------------------------------------------------
// Launch. Input order per metadata: x, Wk, Wq, Wv, Wo
// ---------------------------------------------------------------------------
extern "C" void kernel_launch(void* const* d_in, const int* in_sizes, int n_in,
                              void* d_out, int out_size)
{
    const float* x  = (const float*)d_in[0];
    const float* Wk = (const float*)d_in[1];
    const float* Wq = (const float*)d_in[2];
    const float* Wv = (const float*)d_in[3];
    const float* Wo = (const float*)d_in[4];
    float* out = (float*)d_out;

    cudaFuncSetAttribute(gemm_qkv,
                         cudaFuncAttributeMaxDynamicSharedMemorySize, QKV_SMEM);
    cudaFuncSetAttribute(gemm_out,
                         cudaFuncAttributeMaxDynamicSharedMemorySize, OUT_SMEM);
    cudaFuncSetAttribute(attn_mma,
                         cudaFuncAttributeMaxDynamicSharedMemorySize, ATT_SMEM);

    __half *xh, *xl, *wq, *wk, *wv;
    __nv_bfloat16 *woh, *wol;
    cudaGetSymbolAddress((void**)&xh, g_xh);
    cudaGetSymbolAddress((void**)&xl, g_xl);
    cudaGetSymbolAddress((void**)&wq, g_wq);
    cudaGetSymbolAddress((void**)&wk, g_wk);
    cudaGetSymbolAddress((void**)&wv, g_wv);
    cudaGetSymbolAddress((void**)&woh, g_wo_hi);
    cudaGetSymbolAddress((void**)&wol, g_wo_lo);

    prep_x_kernel<<<1024, 256>>>(x, xh, xl, ROWS * DM);
    prep_w_heads_kernel<<<dim3(32, 2, 16), 256>>>(Wq, wq);
    prep_w_heads_kernel<<<dim3(32, 2, 16), 256>>>(Wk, wk);
    prep_w_heads_kernel<<<dim3(32, 2, 16), 256>>>(Wv, wv);
    prep_wo_kernel<<<dim3(32, 32), 256>>>(Wo, woh, wol);

    gemm_qkv<<<dim3(32, 8, 3), 256, QKV_SMEM>>>(xh, xl);

    attn_mma<<<dim3(S_ / 128, BH), 128, ATT_SMEM>>>();

    gemm_out<<<dim3(32, 8), 256, OUT_SMEM>>>(out);
}

// round 10
// speedup vs baseline: 6.6224x; 1.3029x over previous
#include <cuda_runtime.h>
#include <cuda_bf16.h>
#include <cuda_fp16.h>
#include <math_constants.h>
#include <cstdint>

#define B_  2
#define S_  2048
#define DM  1024
#define DK  64
#define H_  16
#define BH  (B_ * H_)
#define ROWS (B_ * S_)          // 4096

// ---------------------------------------------------------------------------
// Scratch (allocation-free: device globals)
// ---------------------------------------------------------------------------
__device__ __half g_x16[ROWS * DM];
__device__ __half g_wq[DM * DM], g_wk[DM * DM], g_wv[DM * DM];
__device__ __half g_wo[DM * DM];
__device__ __half g_q[BH * S_ * DK], g_k[BH * S_ * DK], g_v[BH * S_ * DK];
__device__ __half g_cxh[ROWS * DM], g_cxl[ROWS * DM];

// Q pre-scale: (1/sqrt(64)) * log2(e)  -> softmax computed in base-2
#define Q_ALPHA 0.18033688011112042f

// ---------------------------------------------------------------------------
// Helpers
// ---------------------------------------------------------------------------
__device__ __forceinline__ uint32_t smem_to_u32(const void* p) {
    uint32_t a;
    asm("{ .reg .u64 t; cvta.to.shared.u64 t, %1; cvt.u32.u64 %0, t; }"
        : "=r"(a) : "l"(p));
    return a;
}
// fp16 mma
__device__ __forceinline__ void mma16816h(float* c, const uint32_t* a, const uint32_t* b) {
    asm volatile("mma.sync.aligned.m16n8k16.row.col.f32.f16.f16.f32 "
        "{%0,%1,%2,%3}, {%4,%5,%6,%7}, {%8,%9}, {%0,%1,%2,%3};"
        : "+f"(c[0]), "+f"(c[1]), "+f"(c[2]), "+f"(c[3])
        : "r"(a[0]), "r"(a[1]), "r"(a[2]), "r"(a[3]), "r"(b[0]), "r"(b[1]));
}
__device__ __forceinline__ void ldsm_x4(uint32_t* r, uint32_t a) {
    asm volatile("ldmatrix.sync.aligned.m8n8.x4.shared.b16 {%0,%1,%2,%3}, [%4];"
        : "=r"(r[0]), "=r"(r[1]), "=r"(r[2]), "=r"(r[3]) : "r"(a));
}
__device__ __forceinline__ void ldsm_x4_t(uint32_t* r, uint32_t a) {
    asm volatile("ldmatrix.sync.aligned.m8n8.x4.trans.shared.b16 {%0,%1,%2,%3}, [%4];"
        : "=r"(r[0]), "=r"(r[1]), "=r"(r[2]), "=r"(r[3]) : "r"(a));
}
__device__ __forceinline__ void cp16(uint32_t d, const void* s) {
    asm volatile("cp.async.cg.shared.global [%0], [%1], 16;" :: "r"(d), "l"(s));
}
#define CP_COMMIT asm volatile("cp.async.commit_group;" ::: "memory")
#define CP_WAIT1  asm volatile("cp.async.wait_group 1;" ::: "memory")
#define CP_WAIT0  asm volatile("cp.async.wait_group 0;" ::: "memory")

__device__ __forceinline__ uint32_t packh(float lo, float hi) {
    uint32_t r;
    asm("cvt.rn.f16x2.f32 %0, %1, %2;" : "=r"(r) : "f"(hi), "f"(lo));
    return r;
}

// ---------------------------------------------------------------------------
// Prep kernels
// ---------------------------------------------------------------------------
__global__ void prep_x_kernel(const float* __restrict__ x,
                              __half* __restrict__ dst, int n)
{
    for (int i = blockIdx.x * blockDim.x + threadIdx.x; i < n;
         i += gridDim.x * blockDim.x)
        dst[i] = __float2half_rn(x[i]);
}

// W[h][k][c] (16x1024x64) -> dst[n=h*64+c][k] single fp16 plane. grid (32,2,16)
__global__ void prep_w_heads_kernel(const float* __restrict__ W,
                                    __half* __restrict__ dst)
{
    __shared__ float tile[32][33];
    int t = threadIdx.x, tx = t & 31, ty = t >> 5;
    int k0 = blockIdx.x * 32, c0 = blockIdx.y * 32, h = blockIdx.z;
    const float* src = W + (size_t)h * DM * DK;
    #pragma unroll
    for (int i = 0; i < 32; i += 8)
        tile[ty + i][tx] = src[(size_t)(k0 + ty + i) * DK + c0 + tx];
    __syncthreads();
    #pragma unroll
    for (int i = 0; i < 32; i += 8) {
        int n = h * 64 + c0 + ty + i;
        dst[(size_t)n * DM + k0 + tx] = __float2half_rn(tile[tx][ty + i]);
    }
}

// Wo[k][n] -> dst[n][k] single fp16 plane. grid (32,32)
__global__ void prep_wo_kernel(const float* __restrict__ W,
                               __half* __restrict__ dst)
{
    __shared__ float tile[32][33];
    int t = threadIdx.x, tx = t & 31, ty = t >> 5;
    int k0 = blockIdx.x * 32, n0 = blockIdx.y * 32;
    #pragma unroll
    for (int i = 0; i < 32; i += 8)
        tile[ty + i][tx] = W[(size_t)(k0 + ty + i) * DM + n0 + tx];
    __syncthreads();
    #pragma unroll
    for (int i = 0; i < 32; i += 8) {
        int n = n0 + ty + i;
        dst[(size_t)n * DM + k0 + tx] = __float2half_rn(tile[tx][ty + i]);
    }
}

// ---------------------------------------------------------------------------
// Common GEMM geometry
// ---------------------------------------------------------------------------
#define GBK 32
#define GSTRIDE 40
#define GPLANE (128 * GSTRIDE * 2)      // 10240 B

// ---------------------------------------------------------------------------
// QKV projection GEMM: fp16 single product (x16*W), fused Q/K/V via z.
// ---------------------------------------------------------------------------
#define QSTAGE (2 * GPLANE)             // 20480 : x, W
#define QKV_SMEM (2 * QSTAGE)           // 40960

__global__ __launch_bounds__(256) void gemm_qkv(const __half* __restrict__ x16)
{
    extern __shared__ char smem[];
    const uint32_t sb = smem_to_u32(smem);
    const int t = threadIdx.x, w = t >> 5, ln = t & 31;
    const int wm = (w & 1) * 64, wn = (w >> 1) * 32;
    const int row0 = blockIdx.x * 128, col0 = blockIdx.y * 128;
    const int z = blockIdx.z;

    const __half* W = (z == 0) ? g_wq : (z == 1) ? g_wk : g_wv;
    __half* out     = (z == 0) ? g_q  : (z == 1) ? g_k  : g_v;
    const float alpha = (z == 0) ? Q_ALPHA : 1.0f;

    const __half* src[2] = { x16 + (size_t)row0 * DM, W + (size_t)col0 * DM };

    const int ldr0 = t >> 2, ldseg = t & 3;

    float c[4][4][4] = {};

    {
        #pragma unroll
        for (int pi = 0; pi < 2; pi++)
            #pragma unroll
            for (int j = 0; j < 2; j++) {
                int row = ldr0 + j * 64;
                cp16(sb + pi * GPLANE + row * 80 + ldseg * 16,
                     src[pi] + (size_t)row * DM + ldseg * 8);
            }
        CP_COMMIT;
    }

    for (int kc = 0; kc < DM / GBK; kc++) {
        if (kc + 1 < DM / GBK) {
            int k0 = (kc + 1) * GBK;
            uint32_t stn = sb + ((kc + 1) & 1) * QSTAGE;
            #pragma unroll
            for (int pi = 0; pi < 2; pi++)
                #pragma unroll
                for (int j = 0; j < 2; j++) {
                    int row = ldr0 + j * 64;
                    cp16(stn + pi * GPLANE + row * 80 + ldseg * 16,
                         src[pi] + (size_t)row * DM + k0 + ldseg * 8);
                }
            CP_COMMIT;
            CP_WAIT1;
        } else {
            CP_WAIT0;
        }
        __syncthreads();
        uint32_t st = sb + (kc & 1) * QSTAGE;

        #pragma unroll
        for (int ks = 0; ks < 2; ks++) {
            uint32_t bh[4][2];
            #pragma unroll
            for (int np = 0; np < 2; np++) {
                uint32_t baddr = st + GPLANE
                    + (wn + np * 16 + ((ln >> 4) & 1) * 8 + (ln & 7)) * 80
                    + ks * 32 + ((ln >> 3) & 1) * 16;
                uint32_t r[4];
                ldsm_x4(r, baddr);
                bh[2*np][0] = r[0]; bh[2*np][1] = r[1];
                bh[2*np+1][0] = r[2]; bh[2*np+1][1] = r[3];
            }
            #pragma unroll
            for (int mi = 0; mi < 4; mi++) {
                uint32_t aaddr = st + (wm + mi * 16 + (ln & 15)) * 80
                               + ks * 32 + (ln >> 4) * 16;
                uint32_t ah[4];
                ldsm_x4(ah, aaddr);
                #pragma unroll
                for (int ni = 0; ni < 4; ni++)
                    mma16816h(c[mi][ni], ah, bh[ni]);
            }
        }
        __syncthreads();
    }

    #pragma unroll
    for (int mi = 0; mi < 4; mi++) {
        int r = row0 + wm + mi * 16 + (ln >> 2);
        #pragma unroll
        for (int ni = 0; ni < 4; ni++) {
            int cc = col0 + wn + ni * 8 + 2 * (ln & 3);
            int h = cc >> 6, d = cc & 63;
            #pragma unroll
            for (int rr = 0; rr < 2; rr++) {
                int row = r + rr * 8;
                int b = row >> 11, s = row & (S_ - 1);
                size_t idx = ((size_t)((b << 4) + h) * S_ + s) * DK + d;
                *(uint32_t*)&out[idx] = packh(c[mi][ni][2*rr] * alpha,
                                              c[mi][ni][2*rr+1] * alpha);
            }
        }
    }
}

// ---------------------------------------------------------------------------
// Output projection GEMM: fp16 2-product (cxh*Wo + cxl*Wo), fp32 out.
// ---------------------------------------------------------------------------
#define OSTAGE (3 * GPLANE)             // 30720 : cxh, cxl, Wo
#define OUT_SMEM (2 * OSTAGE)           // 61440

__global__ __launch_bounds__(256) void gemm_out(float* __restrict__ outf)
{
    extern __shared__ char smem[];
    const uint32_t sb = smem_to_u32(smem);
    const int t = threadIdx.x, w = t >> 5, ln = t & 31;
    const int wm = (w & 1) * 64, wn = (w >> 1) * 32;
    const int row0 = blockIdx.x * 128, col0 = blockIdx.y * 128;

    const __half* src[3] = {
        g_cxh + (size_t)row0 * DM, g_cxl + (size_t)row0 * DM,
        g_wo + (size_t)col0 * DM };

    const int ldr0 = t >> 2, ldseg = t & 3;

    float c[4][4][4] = {};

    {
        #pragma unroll
        for (int pi = 0; pi < 3; pi++)
            #pragma unroll
            for (int j = 0; j < 2; j++) {
                int row = ldr0 + j * 64;
                cp16(sb + pi * GPLANE + row * 80 + ldseg * 16,
                     src[pi] + (size_t)row * DM + ldseg * 8);
            }
        CP_COMMIT;
    }

    for (int kc = 0; kc < DM / GBK; kc++) {
        if (kc + 1 < DM / GBK) {
            int k0 = (kc + 1) * GBK;
            uint32_t stn = sb + ((kc + 1) & 1) * OSTAGE;
            #pragma unroll
            for (int pi = 0; pi < 3; pi++)
                #pragma unroll
                for (int j = 0; j < 2; j++) {
                    int row = ldr0 + j * 64;
                    cp16(stn + pi * GPLANE + row * 80 + ldseg * 16,
                         src[pi] + (size_t)row * DM + k0 + ldseg * 8);
                }
            CP_COMMIT;
            CP_WAIT1;
        } else {
            CP_WAIT0;
        }
        __syncthreads();
        uint32_t st = sb + (kc & 1) * OSTAGE;

        #pragma unroll
        for (int ks = 0; ks < 2; ks++) {
            uint32_t bh[4][2];
            #pragma unroll
            for (int np = 0; np < 2; np++) {
                uint32_t baddr = st + 2 * GPLANE
                    + (wn + np * 16 + ((ln >> 4) & 1) * 8 + (ln & 7)) * 80
                    + ks * 32 + ((ln >> 3) & 1) * 16;
                uint32_t r[4];
                ldsm_x4(r, baddr);
                bh[2*np][0] = r[0]; bh[2*np][1] = r[1];
                bh[2*np+1][0] = r[2]; bh[2*np+1][1] = r[3];
            }
            #pragma unroll
            for (int mi = 0; mi < 4; mi++) {
                uint32_t aaddr = st + (wm + mi * 16 + (ln & 15)) * 80
                               + ks * 32 + (ln >> 4) * 16;
                uint32_t ah[4], al[4];
                ldsm_x4(ah, aaddr);
                ldsm_x4(al, aaddr + GPLANE);
                #pragma unroll
                for (int ni = 0; ni < 4; ni++) {
                    mma16816h(c[mi][ni], ah, bh[ni]);
                    mma16816h(c[mi][ni], al, bh[ni]);
                }
            }
        }
        __syncthreads();
    }

    #pragma unroll
    for (int mi = 0; mi < 4; mi++) {
        int r = row0 + wm + mi * 16 + (ln >> 2);
        #pragma unroll
        for (int ni = 0; ni < 4; ni++) {
            int cc = col0 + wn + ni * 8 + 2 * (ln & 3);
            *(float2*)&outf[(size_t)r * DM + cc] =
                make_float2(c[mi][ni][0], c[mi][ni][1]);
            *(float2*)&outf[(size_t)(r + 8) * DM + cc] =
                make_float2(c[mi][ni][2], c[mi][ni][3]);
        }
    }
}

// ---------------------------------------------------------------------------
// FP16 flash attention: 4 warps, warp tile m=32 x 64 t, 2 CTAs/SM.
// scores = q*k (1 product); PV = p*v (1 product). Softmax base-2.
// Epilogue: ctx -> fp16 hi/lo.
// ---------------------------------------------------------------------------
#define AT_STRIDE 72                     // padded elems (144 B)
#define AT_PLANE (64 * AT_STRIDE * 2)    // 9216 B
#define AT_STAGE (2 * AT_PLANE)          // 18432 : K, V
#define ATT_SMEM (2 * AT_STAGE)          // 36864

__global__ __launch_bounds__(128, 2) void attn_mma()
{
    extern __shared__ char smem[];
    const uint32_t sb = smem_to_u32(smem);
    const int t = threadIdx.x, w = t >> 5, ln = t & 31;
    const int bh = blockIdx.y, q0 = blockIdx.x * 128;
    const size_t hbase = (size_t)bh * S_ * DK;

    // Q fragments (fp16, pre-scaled by Q_ALPHA)
    uint32_t qh[4][8];
    #pragma unroll
    for (int mi = 0; mi < 2; mi++) {
        int r = q0 + w * 32 + mi * 16 + (ln >> 2);
        int cb = 2 * (ln & 3);
        #pragma unroll
        for (int ks = 0; ks < 4; ks++) {
            int c0 = ks * 16 + cb;
            qh[ks][mi*4+0] = *(const uint32_t*)&g_q[hbase + (size_t)r * DK + c0];
            qh[ks][mi*4+1] = *(const uint32_t*)&g_q[hbase + (size_t)(r + 8) * DK + c0];
            qh[ks][mi*4+2] = *(const uint32_t*)&g_q[hbase + (size_t)r * DK + c0 + 8];
            qh[ks][mi*4+3] = *(const uint32_t*)&g_q[hbase + (size_t)(r + 8) * DK + c0 + 8];
        }
    }

    float ctx[2][8][4] = {};
    float mx[2][2], ls[2][2];
    #pragma unroll
    for (int i = 0; i < 2; i++) {
        mx[i][0] = -CUDART_INF_F; mx[i][1] = -CUDART_INF_F;
        ls[i][0] = 0.f; ls[i][1] = 0.f;
    }

    const __half* gsrc[2] = { g_k + hbase, g_v + hbase };
    const int krow = t >> 3, kseg = t & 7;

    {
        #pragma unroll
        for (int pi = 0; pi < 2; pi++)
            #pragma unroll
            for (int j = 0; j < 4; j++) {
                int row = krow + j * 16;
                cp16(sb + pi * AT_PLANE + row * 144 + kseg * 16,
                     gsrc[pi] + (size_t)row * DK + kseg * 8);
            }
        CP_COMMIT;
    }

    for (int it = 0; it < S_ / 64; it++) {
        if (it + 1 < S_ / 64) {
            uint32_t stn = sb + ((it + 1) & 1) * AT_STAGE;
            #pragma unroll
            for (int pi = 0; pi < 2; pi++)
                #pragma unroll
                for (int j = 0; j < 4; j++) {
                    int row = krow + j * 16;
                    cp16(stn + pi * AT_PLANE + row * 144 + kseg * 16,
                         gsrc[pi] + (size_t)((it + 1) * 64 + row) * DK + kseg * 8);
                }
            CP_COMMIT;
            CP_WAIT1;
        } else {
            CP_WAIT0;
        }
        __syncthreads();
        uint32_t st = sb + (it & 1) * AT_STAGE;

        #pragma unroll
        for (int half = 0; half < 2; half++) {
            // ---- scores: single-product fp16 ----
            float sc[2][4][4] = {};
            #pragma unroll
            for (int ks = 0; ks < 4; ks++) {
                #pragma unroll
                for (int np = 0; np < 2; np++) {
                    uint32_t baddr = st
                        + (half * 32 + np * 16 + ((ln >> 4) & 1) * 8 + (ln & 7)) * 144
                        + ks * 32 + ((ln >> 3) & 1) * 16;
                    uint32_t rh[4];
                    ldsm_x4(rh, baddr);
                    uint32_t b0[2] = { rh[0], rh[1] }, b1[2] = { rh[2], rh[3] };
                    #pragma unroll
                    for (int mi = 0; mi < 2; mi++) {
                        mma16816h(sc[mi][2*np],   qh[ks] + mi*4, b0);
                        mma16816h(sc[mi][2*np+1], qh[ks] + mi*4, b1);
                    }
                }
            }

            // ---- online softmax (base-2) ----
            #pragma unroll
            for (int mi = 0; mi < 2; mi++) {
                float rm0 = -CUDART_INF_F, rm1 = -CUDART_INF_F;
                #pragma unroll
                for (int nj = 0; nj < 4; nj++) {
                    rm0 = fmaxf(rm0, fmaxf(sc[mi][nj][0], sc[mi][nj][1]));
                    rm1 = fmaxf(rm1, fmaxf(sc[mi][nj][2], sc[mi][nj][3]));
                }
                rm0 = fmaxf(rm0, __shfl_xor_sync(0xffffffffu, rm0, 1));
                rm0 = fmaxf(rm0, __shfl_xor_sync(0xffffffffu, rm0, 2));
                rm1 = fmaxf(rm1, __shfl_xor_sync(0xffffffffu, rm1, 1));
                rm1 = fmaxf(rm1, __shfl_xor_sync(0xffffffffu, rm1, 2));
                float mn0 = fmaxf(mx[mi][0], rm0), mn1 = fmaxf(mx[mi][1], rm1);
                float a0 = exp2f(mx[mi][0] - mn0), a1 = exp2f(mx[mi][1] - mn1);
                mx[mi][0] = mn0; mx[mi][1] = mn1;
                float rs0 = 0.f, rs1 = 0.f;
                #pragma unroll
                for (int nj = 0; nj < 4; nj++) {
                    sc[mi][nj][0] = exp2f(sc[mi][nj][0] - mn0);
                    sc[mi][nj][1] = exp2f(sc[mi][nj][1] - mn0);
                    sc[mi][nj][2] = exp2f(sc[mi][nj][2] - mn1);
                    sc[mi][nj][3] = exp2f(sc[mi][nj][3] - mn1);
                    rs0 += sc[mi][nj][0] + sc[mi][nj][1];
                    rs1 += sc[mi][nj][2] + sc[mi][nj][3];
                }
                rs0 += __shfl_xor_sync(0xffffffffu, rs0, 1);
                rs0 += __shfl_xor_sync(0xffffffffu, rs0, 2);
                rs1 += __shfl_xor_sync(0xffffffffu, rs1, 1);
                rs1 += __shfl_xor_sync(0xffffffffu, rs1, 2);
                ls[mi][0] = ls[mi][0] * a0 + rs0;
                ls[mi][1] = ls[mi][1] * a1 + rs1;
                #pragma unroll
                for (int vt = 0; vt < 8; vt++) {
                    ctx[mi][vt][0] *= a0; ctx[mi][vt][1] *= a0;
                    ctx[mi][vt][2] *= a1; ctx[mi][vt][3] *= a1;
                }
            }

            // ---- P fragments (fp16) by register reinterleave ----
            uint32_t ph[2][2][4];
            #pragma unroll
            for (int mi = 0; mi < 2; mi++)
                #pragma unroll
                for (int kk = 0; kk < 2; kk++)
                    #pragma unroll
                    for (int e = 0; e < 4; e++) {
                        int tile = 2 * kk + (e >> 1);
                        int o = (e & 1) * 2;
                        ph[mi][kk][e] = packh(sc[mi][tile][o], sc[mi][tile][o + 1]);
                    }

            // ---- ctx += P * V (1 product) ----
            #pragma unroll
            for (int kk = 0; kk < 2; kk++) {
                #pragma unroll
                for (int vp = 0; vp < 4; vp++) {
                    uint32_t vaddr = st + AT_PLANE
                        + (half * 32 + kk * 16 + ((ln >> 3) & 1) * 8 + (ln & 7)) * 144
                        + vp * 32 + ((ln >> 4) & 1) * 16;
                    uint32_t rh[4];
                    ldsm_x4_t(rh, vaddr);
                    uint32_t b0[2] = { rh[0], rh[1] }, b1[2] = { rh[2], rh[3] };
                    #pragma unroll
                    for (int mi = 0; mi < 2; mi++) {
                        mma16816h(ctx[mi][2*vp],   ph[mi][kk], b0);
                        mma16816h(ctx[mi][2*vp+1], ph[mi][kk], b1);
                    }
                }
            }
        }
        __syncthreads();
    }

    // ---- epilogue: ctx -> fp16 hi/lo ----
    const int b = bh >> 4, h = bh & 15;
    #pragma unroll
    for (int mi = 0; mi < 2; mi++) {
        float inv0 = 1.f / ls[mi][0], inv1 = 1.f / ls[mi][1];
        int r = q0 + w * 32 + mi * 16 + (ln >> 2);
        size_t ob0 = ((size_t)(b * S_ + r)) * DM + h * 64;
        size_t ob1 = ob0 + (size_t)8 * DM;
        #pragma unroll
        for (int vt = 0; vt < 8; vt++) {
            int cc = vt * 8 + 2 * (ln & 3);
            float v0 = ctx[mi][vt][0] * inv0, v1 = ctx[mi][vt][1] * inv0;
            float v2 = ctx[mi][vt][2] * inv1, v3 = ctx[mi][vt][3] * inv1;
            uint32_t pA = packh(v0, v1);
            uint32_t pB = packh(v2, v3);
            *(uint32_t*)&g_cxh[ob0 + cc] = pA;
            *(uint32_t*)&g_cxh[ob1 + cc] = pB;
            __half2 hA = *(__half2*)&pA, hB = *(__half2*)&pB;
            *(uint32_t*)&g_cxl[ob0 + cc] =
                packh(v0 - __half2float(__low2half(hA)),
                      v1 - __half2float(__high2half(hA)));
            *(uint32_t*)&g_cxl[ob1 + cc] =
                packh(v2 - __half2float(__low2half(hB)),
                      v3 - __half2float(__high2half(hB)));
        }
    }
}

// ---------------------------------------------------------------------------
// Launch. Input order per metadata: x, Wk, Wq, Wv, Wo
// ---------------------------------------------------------------------------
extern "C" void kernel_launch(void* const* d_in, const int* in_sizes, int n_in,
                              void* d_out, int out_size)
{
    const float* x  = (const float*)d_in[0];
    const float* Wk = (const float*)d_in[1];
    const float* Wq = (const float*)d_in[2];
    const float* Wv = (const float*)d_in[3];
    const float* Wo = (const float*)d_in[4];
    float* out = (float*)d_out;

    cudaFuncSetAttribute(gemm_qkv,
                         cudaFuncAttributeMaxDynamicSharedMemorySize, QKV_SMEM);
    cudaFuncSetAttribute(gemm_out,
                         cudaFuncAttributeMaxDynamicSharedMemorySize, OUT_SMEM);
    cudaFuncSetAttribute(attn_mma,
                         cudaFuncAttributeMaxDynamicSharedMemorySize, ATT_SMEM);

    __half *x16, *wq, *wk, *wv, *wo;
    cudaGetSymbolAddress((void**)&x16, g_x16);
    cudaGetSymbolAddress((void**)&wq, g_wq);
    cudaGetSymbolAddress((void**)&wk, g_wk);
    cudaGetSymbolAddress((void**)&wv, g_wv);
    cudaGetSymbolAddress((void**)&wo, g_wo);

    prep_x_kernel<<<1024, 256>>>(x, x16, ROWS * DM);
    prep_w_heads_kernel<<<dim3(32, 2, 16), 256>>>(Wq, wq);
    prep_w_heads_kernel<<<dim3(32, 2, 16), 256>>>(Wk, wk);
    prep_w_heads_kernel<<<dim3(32, 2, 16), 256>>>(Wv, wv);
    prep_wo_kernel<<<dim3(32, 32), 256>>>(Wo, wo);

    gemm_qkv<<<dim3(32, 8, 3), 256, QKV_SMEM>>>(x16);

    attn_mma<<<dim3(S_ / 128, BH), 128, ATT_SMEM>>>();

    gemm_out<<<dim3(32, 8), 256, OUT_SMEM>>>(out);
}